// round 7
// baseline (speedup 1.0000x reference)
#include <cuda_runtime.h>
#include <cuda_bf16.h>
#include <math.h>

#define B_ 4
#define L_ 2048
#define H_ 512
#define N_ 8
#define D_ 64

typedef unsigned long long ull;

__device__ __forceinline__ ull pack2f(float lo, float hi) {
    ull r; asm("mov.b64 %0, {%1, %2};" : "=l"(r) : "f"(lo), "f"(hi)); return r;
}
__device__ __forceinline__ void unpack2f(ull v, float& lo, float& hi) {
    asm("mov.b64 {%0, %1}, %2;" : "=f"(lo), "=f"(hi) : "l"(v));
}
__device__ __forceinline__ ull fma2f(ull a, ull b, ull c) {
    ull d; asm("fma.rn.f32x2 %0, %1, %2, %3;" : "=l"(d) : "l"(a), "l"(b), "l"(c)); return d;
}
__device__ __forceinline__ ull mul2f(ull a, ull b) {
    ull d; asm("mul.rn.f32x2 %0, %1, %2;" : "=l"(d) : "l"(a), "l"(b)); return d;
}

// ---------------- scratch ----------------
__device__ float g_Wqkv[H_ * 3 * H_];
__device__ float g_bqkv[3 * H_];
__device__ float g_Wrp[H_ * H_];
__device__ float g_brp[H_];
__device__ float g_WcT[H_ * H_];
__device__ float g_W1T[H_ * H_];
__device__ float g_W2T[H_ * H_];
__device__ float g_q[B_ * N_ * L_ * D_];
__device__ float g_k[B_ * N_ * L_ * D_];
__device__ float g_v[B_ * N_ * L_ * D_];
__device__ float g_rb[N_ * L_ * D_];
__device__ float g_pw[N_ * L_];
__device__ float g_attn[B_ * L_ * H_];
__device__ float g_y1[B_ * L_ * H_];
__device__ float g_a[B_ * L_ * H_];
__device__ float g_h1[B_ * L_ * H_];
__device__ float g_y2[B_ * L_ * H_];

// ---------------- pack weights ----------------
__global__ void pack_kernel(const float* __restrict__ Wq, const float* __restrict__ bq,
                            const float* __restrict__ Wk, const float* __restrict__ bk,
                            const float* __restrict__ Wv, const float* __restrict__ bv,
                            const float* __restrict__ Wr, const float* __restrict__ br,
                            const float* __restrict__ Wc, const float* __restrict__ W1,
                            const float* __restrict__ W2) {
    int idx = blockIdx.x * blockDim.x + threadIdx.x;
    int stride = gridDim.x * blockDim.x;
    for (int i = idx; i < 512 * 1536; i += stride) {
        int h = i / 1536, c = i % 1536;
        int mat = c >> 9, rem = c & 511, n = rem >> 6, d = rem & 63;
        const float* W = (mat == 0) ? Wq : ((mat == 1) ? Wk : Wv);
        g_Wqkv[i] = W[(n * 512 + h) * 64 + d];
    }
    for (int i = idx; i < 1536; i += stride) {
        int mat = i >> 9, rem = i & 511;
        const float* bb = (mat == 0) ? bq : ((mat == 1) ? bk : bv);
        g_bqkv[i] = bb[rem];
    }
    for (int i = idx; i < 512 * 512; i += stride) {
        int h = i >> 9, c = i & 511;
        int n = c >> 6, d = c & 63;
        g_Wrp[i] = Wr[(n * 512 + h) * 64 + d];
    }
    for (int i = idx; i < 512; i += stride) g_brp[i] = br[i];
    for (int i = idx; i < 512 * 512; i += stride) {
        int k = i >> 9, c = i & 511;
        g_WcT[i] = Wc[c * 512 + k];
        g_W1T[i] = W1[c * 512 + k];
        g_W2T[i] = W2[c * 512 + k];
    }
}

// pw[n][p] = sum_d (pb-cb)[n][d] * r[n][p][d]
__global__ void pw_kernel(const float* __restrict__ cb, const float* __restrict__ pb,
                          float* __restrict__ pwg) {
    int n = blockIdx.y;
    int p = blockIdx.x * 128 + threadIdx.x;
    const float* rp = &g_rb[(n * 2048 + p) * 64];
    float s = 0.f;
#pragma unroll 16
    for (int d = 0; d < 64; d++) s += (pb[n * 64 + d] - cb[n * 64 + d]) * rp[d];
    pwg[n * 2048 + p] = s;
}

__device__ __forceinline__ float gelu_f(float v) {
    return 0.5f * v * (1.0f + erff(v * 0.70710678118654752f));
}

// ---------------- 128x128-tile SGEMM, f32x2, K=512 ----------------
// MODE 0: qkv scatter (+bqkv)  MODE 1: r scatter (+brp)
// MODE 2: acc+bias+res         MODE 3: gelu(acc+bias)
template <int MODE>
__global__ void __launch_bounds__(256, 2)
gemm128(const float* __restrict__ A, const float* __restrict__ Bm,
        const float* __restrict__ bias, const float* __restrict__ res,
        float* __restrict__ C, int Nc,
        float* __restrict__ qd, float* __restrict__ kd, float* __restrict__ vd) {
    __shared__ float As[8][260];   // duplicated along m
    __shared__ float Bs[8][132];
    const int tid = threadIdx.x;
    const int tx = tid & 15, ty = tid >> 4;
    const int m0 = blockIdx.y * 128, c0 = blockIdx.x * 128;
    const int am = tid >> 1, ak = (tid & 1) * 4;
    const int bk = tid >> 5, bc = (tid & 31) * 4;

    const float* Ap = A + (size_t)(m0 + am) * 512 + ak;
    const float* Bp = Bm + (size_t)bk * Nc + c0 + bc;

    ull acc[8][4];
#pragma unroll
    for (int r = 0; r < 8; r++)
#pragma unroll
        for (int c = 0; c < 4; c++) acc[r][c] = 0ULL;

    float4 ar = *(const float4*)Ap;
    float4 br = *(const float4*)Bp;

    for (int k0 = 0; k0 < 512; k0 += 8) {
        As[ak + 0][am * 2] = ar.x; As[ak + 0][am * 2 + 1] = ar.x;
        As[ak + 1][am * 2] = ar.y; As[ak + 1][am * 2 + 1] = ar.y;
        As[ak + 2][am * 2] = ar.z; As[ak + 2][am * 2 + 1] = ar.z;
        As[ak + 3][am * 2] = ar.w; As[ak + 3][am * 2 + 1] = ar.w;
        *(float4*)&Bs[bk][bc] = br;
        __syncthreads();
        if (k0 + 8 < 512) {
            ar = *(const float4*)(Ap + k0 + 8);
            br = *(const float4*)(Bp + (size_t)(k0 + 8) * Nc);
        }
#pragma unroll
        for (int kk = 0; kk < 8; kk++) {
            ull a2[8];
#pragma unroll
            for (int r = 0; r < 8; r++)
                a2[r] = *(const ull*)&As[kk][(ty * 8 + r) * 2];
            ulonglong2 b0 = *(const ulonglong2*)&Bs[kk][tx * 8];
            ulonglong2 b1 = *(const ulonglong2*)&Bs[kk][tx * 8 + 4];
#pragma unroll
            for (int r = 0; r < 8; r++) {
                acc[r][0] = fma2f(a2[r], b0.x, acc[r][0]);
                acc[r][1] = fma2f(a2[r], b0.y, acc[r][1]);
                acc[r][2] = fma2f(a2[r], b1.x, acc[r][2]);
                acc[r][3] = fma2f(a2[r], b1.y, acc[r][3]);
            }
        }
        __syncthreads();
    }

#pragma unroll
    for (int r = 0; r < 8; r++) {
        float cv[8];
        unpack2f(acc[r][0], cv[0], cv[1]);
        unpack2f(acc[r][1], cv[2], cv[3]);
        unpack2f(acc[r][2], cv[4], cv[5]);
        unpack2f(acc[r][3], cv[6], cv[7]);
        int m = m0 + ty * 8 + r;
#pragma unroll
        for (int c = 0; c < 8; c++) {
            int cg = c0 + tx * 8 + c;
            float val = cv[c] + bias[cg];
            if (MODE == 0) {
                int mat = cg >> 9, rem = cg & 511, n = rem >> 6, d = rem & 63;
                float* dst = (mat == 0) ? qd : ((mat == 1) ? kd : vd);
                int bI = m >> 11, l = m & 2047;
                dst[((bI * 8 + n) * 2048 + l) * 64 + d] = val;
            } else if (MODE == 1) {
                int n = cg >> 6, d = cg & 63;
                C[(n * 2048 + m) * 64 + d] = val;
            } else if (MODE == 2) {
                C[(size_t)m * Nc + cg] = val + res[(size_t)m * Nc + cg];
            } else {
                C[(size_t)m * Nc + cg] = gelu_f(val);
            }
        }
    }
}

// ---------------- fused causal rel-pos flash attention, f32x2 ----------------
// s[i,j] = (qc[i]·k[j] + qc[i]·r[p] + pw[p]) / 8,  p = L-1-i+j, causal.
#define ATTN_SMEM_BYTES ((4 * 64 * 68 + 64 * 132 + 128) * 4)

__global__ void attn_kernel(const float* __restrict__ qg, const float* __restrict__ kg,
                            const float* __restrict__ vg, const float* __restrict__ rg,
                            const float* __restrict__ cb, const float* __restrict__ pwg,
                            float* __restrict__ outg) {
    extern __shared__ float sm[];
    float* Qcs = sm;                      // [64][68] (i,d)
    float* Kst = sm + 4352;               // [64][68] (d,j)
    float* Vs  = sm + 2 * 4352;           // [64][68] (j,d)
    float* Ss  = sm + 3 * 4352;           // [64][68]
    float* Rst = sm + 4 * 4352;           // [64][132] (d,pp)
    float* pws = sm + 4 * 4352 + 8448;    // [128]

    const int tid = threadIdx.x;
    const int tx = tid & 15, ty = tid >> 4;
    const int ib = blockIdx.x, bn = blockIdx.y;
    const int n = bn & 7, b = bn >> 3;
    const int I0 = ib * 64;

    const int lrow = tid >> 4;
    const int ld0 = (tid & 15) * 4;

    const float* qbase = qg + (bn * L_ + I0) * D_;
    float4 cbv = *(const float4*)&cb[n * 64 + ld0];
#pragma unroll
    for (int t = 0; t < 4; t++) {
        int rr = lrow + t * 16;
        float4 qv = *(const float4*)&qbase[rr * 64 + ld0];
        float* dst = &Qcs[rr * 68 + ld0];
        dst[0] = qv.x + cbv.x;
        dst[1] = qv.y + cbv.y;
        dst[2] = qv.z + cbv.z;
        dst[3] = qv.w + cbv.w;
    }

    float mrow[4], lsum[4];
    ull o2[4][2];
#pragma unroll
    for (int r = 0; r < 4; r++) {
        mrow[r] = -1e30f; lsum[r] = 0.f;
        o2[r][0] = 0ULL; o2[r][1] = 0ULL;
    }

    const int r0 = ty * 4, c0 = tx * 4;
    const int wbase = 60 - r0 + c0;

    for (int jb = 0; jb <= ib; jb++) {
        __syncthreads();
        const int J0 = jb * 64;
        const int pmin = L_ - 64 - I0 + J0;
        const float* kbase = kg + (bn * L_ + J0) * D_;
        const float* vbase = vg + (bn * L_ + J0) * D_;
#pragma unroll
        for (int t = 0; t < 4; t++) {
            int j = lrow + t * 16;
            float4 kv = *(const float4*)&kbase[j * 64 + ld0];
            Kst[(ld0 + 0) * 68 + j] = kv.x;
            Kst[(ld0 + 1) * 68 + j] = kv.y;
            Kst[(ld0 + 2) * 68 + j] = kv.z;
            Kst[(ld0 + 3) * 68 + j] = kv.w;
            *(float4*)&Vs[j * 68 + ld0] = *(const float4*)&vbase[j * 64 + ld0];
        }
        const float* rbase = rg + n * (L_ * D_);
#pragma unroll
        for (int t = 0; t < 8; t++) {
            int pp = lrow + t * 16;
            int p = pmin + pp;
            float4 rv = make_float4(0.f, 0.f, 0.f, 0.f);
            if (p < L_) rv = *(const float4*)&rbase[p * 64 + ld0];
            Rst[(ld0 + 0) * 132 + pp] = rv.x;
            Rst[(ld0 + 1) * 132 + pp] = rv.y;
            Rst[(ld0 + 2) * 132 + pp] = rv.z;
            Rst[(ld0 + 3) * 132 + pp] = rv.w;
        }
        if (tid < 128) {
            int p = pmin + tid;
            pws[tid] = (p < L_) ? pwg[n * 2048 + p] : 0.f;
        }
        __syncthreads();

        ull s2[4][2];
#pragma unroll
        for (int r = 0; r < 4; r++) { s2[r][0] = 0ULL; s2[r][1] = 0ULL; }

#pragma unroll 4
        for (int kk = 0; kk < 64; kk++) {
            ull a2[4];
#pragma unroll
            for (int r = 0; r < 4; r++) {
                float aq = Qcs[(r0 + r) * 68 + kk];
                a2[r] = pack2f(aq, aq);
            }
            ulonglong2 kb = *(const ulonglong2*)&Kst[kk * 68 + c0];
            float4 w0 = *(const float4*)&Rst[kk * 132 + wbase];
            float4 w1 = *(const float4*)&Rst[kk * 132 + wbase + 4];
            ull p01 = pack2f(w0.x, w0.y), p12 = pack2f(w0.y, w0.z);
            ull p23 = pack2f(w0.z, w0.w), p34 = pack2f(w0.w, w1.x);
            ull p45 = pack2f(w1.x, w1.y), p56 = pack2f(w1.y, w1.z);
            s2[3][0] = fma2f(a2[3], kb.x, s2[3][0]); s2[3][1] = fma2f(a2[3], kb.y, s2[3][1]);
            s2[3][0] = fma2f(a2[3], p01, s2[3][0]);  s2[3][1] = fma2f(a2[3], p23, s2[3][1]);
            s2[2][0] = fma2f(a2[2], kb.x, s2[2][0]); s2[2][1] = fma2f(a2[2], kb.y, s2[2][1]);
            s2[2][0] = fma2f(a2[2], p12, s2[2][0]);  s2[2][1] = fma2f(a2[2], p34, s2[2][1]);
            s2[1][0] = fma2f(a2[1], kb.x, s2[1][0]); s2[1][1] = fma2f(a2[1], kb.y, s2[1][1]);
            s2[1][0] = fma2f(a2[1], p23, s2[1][0]);  s2[1][1] = fma2f(a2[1], p45, s2[1][1]);
            s2[0][0] = fma2f(a2[0], kb.x, s2[0][0]); s2[0][1] = fma2f(a2[0], kb.y, s2[0][1]);
            s2[0][0] = fma2f(a2[0], p34, s2[0][0]);  s2[0][1] = fma2f(a2[0], p56, s2[0][1]);
        }

        float s[4][4];
#pragma unroll
        for (int r = 0; r < 4; r++) {
            unpack2f(s2[r][0], s[r][0], s[r][1]);
            unpack2f(s2[r][1], s[r][2], s[r][3]);
        }
        const bool diag = (jb == ib);
#pragma unroll
        for (int r = 0; r < 4; r++)
#pragma unroll
            for (int c = 0; c < 4; c++) {
                s[r][c] = (s[r][c] + pws[wbase + 3 - r + c]) * 0.125f;
                if (diag && (J0 + c0 + c) > (I0 + r0 + r)) s[r][c] = -1e30f;
            }

#pragma unroll
        for (int r = 0; r < 4; r++) {
            float rm = fmaxf(fmaxf(s[r][0], s[r][1]), fmaxf(s[r][2], s[r][3]));
#pragma unroll
            for (int mk = 8; mk >= 1; mk >>= 1)
                rm = fmaxf(rm, __shfl_xor_sync(0xffffffffu, rm, mk));
            float mn = fmaxf(mrow[r], rm);
            float alpha = __expf(mrow[r] - mn);
            mrow[r] = mn;
            float rs = 0.f;
#pragma unroll
            for (int c = 0; c < 4; c++) {
                s[r][c] = __expf(s[r][c] - mn);
                rs += s[r][c];
            }
#pragma unroll
            for (int mk = 8; mk >= 1; mk >>= 1)
                rs += __shfl_xor_sync(0xffffffffu, rs, mk);
            lsum[r] = lsum[r] * alpha + rs;
            ull al2 = pack2f(alpha, alpha);
            o2[r][0] = mul2f(o2[r][0], al2);
            o2[r][1] = mul2f(o2[r][1], al2);
        }

#pragma unroll
        for (int r = 0; r < 4; r++)
            *(float4*)&Ss[(r0 + r) * 68 + c0] = make_float4(s[r][0], s[r][1], s[r][2], s[r][3]);
        __syncthreads();

#pragma unroll 4
        for (int jj = 0; jj < 64; jj++) {
            ull a2[4];
#pragma unroll
            for (int r = 0; r < 4; r++) {
                float av = Ss[(r0 + r) * 68 + jj];
                a2[r] = pack2f(av, av);
            }
            ulonglong2 bv = *(const ulonglong2*)&Vs[jj * 68 + c0];
#pragma unroll
            for (int r = 0; r < 4; r++) {
                o2[r][0] = fma2f(a2[r], bv.x, o2[r][0]);
                o2[r][1] = fma2f(a2[r], bv.y, o2[r][1]);
            }
        }
    }

#pragma unroll
    for (int r = 0; r < 4; r++) {
        float inv = 1.0f / lsum[r];
        float o0, o1, o2v, o3;
        unpack2f(o2[r][0], o0, o1);
        unpack2f(o2[r][1], o2v, o3);
        float* od = &outg[(size_t)(b * L_ + I0 + r0 + r) * H_ + n * 64 + c0];
        *(float4*)od = make_float4(o0 * inv, o1 * inv, o2v * inv, o3 * inv);
    }
}

// ---------------- layernorm ----------------
__global__ void ln_kernel(const float* __restrict__ in, const float* __restrict__ w,
                          const float* __restrict__ bparm, float* __restrict__ out) {
    __shared__ float red[8];
    __shared__ float stat[2];
    int row = blockIdx.x, tid = threadIdx.x;
    const float* xr = in + (size_t)row * H_;
    float v0 = xr[tid], v1 = xr[tid + 256];
    float s = v0 + v1;
#pragma unroll
    for (int mk = 16; mk >= 1; mk >>= 1) s += __shfl_xor_sync(0xffffffffu, s, mk);
    if ((tid & 31) == 0) red[tid >> 5] = s;
    __syncthreads();
    if (tid == 0) {
        float t = 0;
#pragma unroll
        for (int i = 0; i < 8; i++) t += red[i];
        stat[0] = t * (1.0f / H_);
    }
    __syncthreads();
    float u = stat[0];
    float d0 = v0 - u, d1 = v1 - u;
    float q = d0 * d0 + d1 * d1;
#pragma unroll
    for (int mk = 16; mk >= 1; mk >>= 1) q += __shfl_xor_sync(0xffffffffu, q, mk);
    __syncthreads();
    if ((tid & 31) == 0) red[tid >> 5] = q;
    __syncthreads();
    if (tid == 0) {
        float t = 0;
#pragma unroll
        for (int i = 0; i < 8; i++) t += red[i];
        stat[1] = rsqrtf(t * (1.0f / H_) + 1e-12f);
    }
    __syncthreads();
    float inv = stat[1];
    out[(size_t)row * H_ + tid] = w[tid] * d0 * inv + bparm[tid];
    out[(size_t)row * H_ + tid + 256] = w[tid + 256] * d1 * inv + bparm[tid + 256];
}

// ---------------- launch ----------------
extern "C" void kernel_launch(void* const* d_in, const int* in_sizes, int n_in,
                              void* d_out, int out_size) {
    (void)in_sizes; (void)n_in; (void)out_size;
    const float* x  = (const float*)d_in[0];
    const float* pe = (const float*)d_in[1];
    const float* Wq = (const float*)d_in[2];
    const float* bq = (const float*)d_in[3];
    const float* Wk = (const float*)d_in[4];
    const float* bk = (const float*)d_in[5];
    const float* Wv = (const float*)d_in[6];
    const float* bv = (const float*)d_in[7];
    const float* Wr = (const float*)d_in[8];
    const float* br = (const float*)d_in[9];
    const float* cb = (const float*)d_in[10];
    const float* pb = (const float*)d_in[11];
    const float* Wc = (const float*)d_in[12];
    const float* bc = (const float*)d_in[13];
    const float* W1 = (const float*)d_in[14];
    const float* b1 = (const float*)d_in[15];
    const float* W2 = (const float*)d_in[16];
    const float* b2 = (const float*)d_in[17];
    const float* lnw = (const float*)d_in[18];
    const float* lnb = (const float*)d_in[19];
    float* out = (float*)d_out;

    float *pWqkv, *pbqkv, *pWrp, *pbrp, *pWcT, *pW1T, *pW2T;
    float *pq, *pk, *pv, *pr, *ppw, *pattn, *py1, *pa, *ph1, *py2;
    cudaGetSymbolAddress((void**)&pWqkv, g_Wqkv);
    cudaGetSymbolAddress((void**)&pbqkv, g_bqkv);
    cudaGetSymbolAddress((void**)&pWrp, g_Wrp);
    cudaGetSymbolAddress((void**)&pbrp, g_brp);
    cudaGetSymbolAddress((void**)&pWcT, g_WcT);
    cudaGetSymbolAddress((void**)&pW1T, g_W1T);
    cudaGetSymbolAddress((void**)&pW2T, g_W2T);
    cudaGetSymbolAddress((void**)&pq, g_q);
    cudaGetSymbolAddress((void**)&pk, g_k);
    cudaGetSymbolAddress((void**)&pv, g_v);
    cudaGetSymbolAddress((void**)&pr, g_rb);
    cudaGetSymbolAddress((void**)&ppw, g_pw);
    cudaGetSymbolAddress((void**)&pattn, g_attn);
    cudaGetSymbolAddress((void**)&py1, g_y1);
    cudaGetSymbolAddress((void**)&pa, g_a);
    cudaGetSymbolAddress((void**)&ph1, g_h1);
    cudaGetSymbolAddress((void**)&py2, g_y2);

    cudaFuncSetAttribute(attn_kernel, cudaFuncAttributeMaxDynamicSharedMemorySize,
                         ATTN_SMEM_BYTES);

    pack_kernel<<<768, 256>>>(Wq, bq, Wk, bk, Wv, bv, Wr, br, Wc, W1, W2);

    // QKV: (8192x512)@(512x1536) scatter
    gemm128<0><<<dim3(12, 64), 256>>>(x, pWqkv, pbqkv, nullptr, nullptr, 1536, pq, pk, pv);

    // R: (2048x512)@(512x512) scatter
    gemm128<1><<<dim3(4, 16), 256>>>(pe, pWrp, pbrp, nullptr, pr, 512, nullptr, nullptr, nullptr);

    // pw[n][p]
    pw_kernel<<<dim3(16, 8), 128>>>(cb, pb, ppw);

    // attention
    attn_kernel<<<dim3(L_ / 64, B_ * N_), 256, ATTN_SMEM_BYTES>>>(pq, pk, pv, pr, cb, ppw, pattn);

    // Wc + residual
    gemm128<2><<<dim3(4, 64), 256>>>(pattn, pWcT, bc, x, py1, 512, nullptr, nullptr, nullptr);

    ln_kernel<<<B_ * L_, 256>>>(py1, lnw, lnb, pa);

    gemm128<3><<<dim3(4, 64), 256>>>(pa, pW1T, b1, nullptr, ph1, 512, nullptr, nullptr, nullptr);

    gemm128<2><<<dim3(4, 64), 256>>>(ph1, pW2T, b2, pa, py2, 512, nullptr, nullptr, nullptr);

    ln_kernel<<<B_ * L_, 256>>>(py2, lnw, lnb, out);
}

// round 9
// speedup vs baseline: 1.3230x; 1.3230x over previous
#include <cuda_runtime.h>
#include <cuda_bf16.h>
#include <math.h>
#include <stdint.h>

#define B_ 4
#define L_ 2048
#define H_ 512
#define N_ 8
#define D_ 64

typedef unsigned long long ull;

// ================= f32x2 helpers (attention) =================
__device__ __forceinline__ ull pack2f(float lo, float hi) {
    ull r; asm("mov.b64 %0, {%1, %2};" : "=l"(r) : "f"(lo), "f"(hi)); return r;
}
__device__ __forceinline__ void unpack2f(ull v, float& lo, float& hi) {
    asm("mov.b64 {%0, %1}, %2;" : "=f"(lo), "=f"(hi) : "l"(v));
}
__device__ __forceinline__ ull fma2f(ull a, ull b, ull c) {
    ull d; asm("fma.rn.f32x2 %0, %1, %2, %3;" : "=l"(d) : "l"(a), "l"(b), "l"(c)); return d;
}
__device__ __forceinline__ ull mul2f(ull a, ull b) {
    ull d; asm("mul.rn.f32x2 %0, %1, %2;" : "=l"(d) : "l"(a), "l"(b)); return d;
}

// ================= HMMA helpers =================
__device__ __forceinline__ uint32_t smem_to_u32(const void* p) {
    uint32_t a;
    asm("{ .reg .u64 t; cvta.to.shared.u64 t, %1; cvt.u32.u64 %0, t; }" : "=r"(a) : "l"(p));
    return a;
}

#define LDSM_X4(r, addr)                                                          \
    asm volatile("ldmatrix.sync.aligned.m8n8.x4.shared.b16 {%0,%1,%2,%3}, [%4];"  \
        : "=r"((r)[0]), "=r"((r)[1]), "=r"((r)[2]), "=r"((r)[3]) : "r"(addr))

__device__ __forceinline__ void mma_bf16(float* c, const uint32_t* a, uint32_t b0, uint32_t b1) {
    asm volatile(
        "mma.sync.aligned.m16n8k16.row.col.f32.bf16.bf16.f32 "
        "{%0,%1,%2,%3}, {%4,%5,%6,%7}, {%8,%9}, {%0,%1,%2,%3};"
        : "+f"(c[0]), "+f"(c[1]), "+f"(c[2]), "+f"(c[3])
        : "r"(a[0]), "r"(a[1]), "r"(a[2]), "r"(a[3]), "r"(b0), "r"(b1));
}

#define CP_ASYNC16(dst, src) asm volatile("cp.async.cg.shared.global [%0], [%1], 16;" :: "r"(dst), "l"(src))
#define CP_COMMIT()          asm volatile("cp.async.commit_group;" ::: "memory")
#define CP_WAIT(n)           asm volatile("cp.async.wait_group %0;" :: "n"(n) : "memory")

// ================= scratch =================
__device__ __nv_bfloat16 g_xh[B_ * L_ * H_];
__device__ __nv_bfloat16 g_xl[B_ * L_ * H_];
__device__ __nv_bfloat16 g_peh[L_ * H_];
__device__ __nv_bfloat16 g_pel[L_ * H_];
__device__ __nv_bfloat16 g_Bqkvh[3 * H_ * H_];
__device__ __nv_bfloat16 g_Bqkvl[3 * H_ * H_];
__device__ __nv_bfloat16 g_Brh[H_ * H_];
__device__ __nv_bfloat16 g_Brl[H_ * H_];
__device__ __nv_bfloat16 g_Wch[H_ * H_];
__device__ __nv_bfloat16 g_Wcl[H_ * H_];
__device__ __nv_bfloat16 g_W1h[H_ * H_];
__device__ __nv_bfloat16 g_W1l[H_ * H_];
__device__ __nv_bfloat16 g_W2h[H_ * H_];
__device__ __nv_bfloat16 g_W2l[H_ * H_];
__device__ float g_bqkv[3 * H_];
__device__ float g_brp[H_];
__device__ float g_q[B_ * N_ * L_ * D_];
__device__ float g_k[B_ * N_ * L_ * D_];
__device__ float g_v[B_ * N_ * L_ * D_];
__device__ float g_rb[N_ * L_ * D_];
__device__ float g_pw[N_ * L_];
__device__ __nv_bfloat16 g_attnh[B_ * L_ * H_];
__device__ __nv_bfloat16 g_attnl[B_ * L_ * H_];
__device__ float g_y1[B_ * L_ * H_];
__device__ float g_a[B_ * L_ * H_];
__device__ __nv_bfloat16 g_ah[B_ * L_ * H_];
__device__ __nv_bfloat16 g_al[B_ * L_ * H_];
__device__ __nv_bfloat16 g_h1h[B_ * L_ * H_];
__device__ __nv_bfloat16 g_h1l[B_ * L_ * H_];
__device__ float g_y2[B_ * L_ * H_];

// ================= split-convert =================
__device__ __forceinline__ void split_bf16(float v, __nv_bfloat16& h, __nv_bfloat16& l) {
    h = __float2bfloat16(v);
    l = __float2bfloat16(v - __bfloat162float(h));
}

__global__ void conv_split(const float* __restrict__ src, __nv_bfloat16* __restrict__ dh,
                           __nv_bfloat16* __restrict__ dl, int n) {
    int i = blockIdx.x * 256 + threadIdx.x;
    int stride = gridDim.x * 256;
    for (; i < n; i += stride) {
        __nv_bfloat16 h, l;
        split_bf16(src[i], h, l);
        dh[i] = h; dl[i] = l;
    }
}

__global__ void pack_qkvr(const float* __restrict__ Wq, const float* __restrict__ bq,
                          const float* __restrict__ Wk, const float* __restrict__ bk,
                          const float* __restrict__ Wv, const float* __restrict__ bv,
                          const float* __restrict__ Wr, const float* __restrict__ br) {
    int idx = blockIdx.x * 256 + threadIdx.x;
    int stride = gridDim.x * 256;
    for (int i = idx; i < 1536 * 512; i += stride) {
        int c = i >> 9, h = i & 511;
        int mat = c >> 9, rem = c & 511, n = rem >> 6, d = rem & 63;
        const float* W = (mat == 0) ? Wq : ((mat == 1) ? Wk : Wv);
        __nv_bfloat16 hh, ll;
        split_bf16(W[(n * 512 + h) * 64 + d], hh, ll);
        g_Bqkvh[i] = hh; g_Bqkvl[i] = ll;
    }
    for (int i = idx; i < 512 * 512; i += stride) {
        int c = i >> 9, h = i & 511;
        int n = c >> 6, d = c & 63;
        __nv_bfloat16 hh, ll;
        split_bf16(Wr[(n * 512 + h) * 64 + d], hh, ll);
        g_Brh[i] = hh; g_Brl[i] = ll;
    }
    for (int i = idx; i < 1536; i += stride) {
        int mat = i >> 9, rem = i & 511;
        const float* bb = (mat == 0) ? bq : ((mat == 1) ? bk : bv);
        g_bqkv[i] = bb[rem];
    }
    for (int i = idx; i < 512; i += stride) g_brp[i] = br[i];
}

__global__ void pw_kernel(const float* __restrict__ cb, const float* __restrict__ pb,
                          float* __restrict__ pwg) {
    int n = blockIdx.y;
    int p = blockIdx.x * 128 + threadIdx.x;
    const float* rp = &g_rb[(n * 2048 + p) * 64];
    float s = 0.f;
#pragma unroll 16
    for (int d = 0; d < 64; d++) s += (pb[n * 64 + d] - cb[n * 64 + d]) * rp[d];
    pwg[n * 2048 + p] = s;
}

__device__ __forceinline__ float gelu_f(float v) {
    return 0.5f * v * (1.0f + erff(v * 0.70710678118654752f));
}

// ================= HMMA GEMM: block tile 128x64, warp tile 32x32, K=512 =================
// D = Ah*Bh^T + Ah*Bl^T + Al*Bh^T   (fp32 accum, mma.sync bf16)
// A planes: [M][512] row-major bf16.  B planes: [Nc][512] row-major (= B^T, i.e. col-major B).
// MODE 0: qkv scatter (+g_bqkv)   MODE 1: r scatter (+g_brp)
// MODE 2: Cf = acc + bias + res   MODE 3: gelu(acc+bias) -> Ch/Cl planes
#define GSTRIDE 80                       // bytes per smem row (32 bf16 + 8 pad)
#define OFF_AH 0
#define OFF_AL 10240
#define OFF_BH 20480
#define OFF_BL 25600
#define BUF_SZ 30720
#define HMMA_SMEM (2 * BUF_SZ + 128)

template <int MODE>
__global__ void __launch_bounds__(256, 2)
gemm_hmma(const __nv_bfloat16* __restrict__ Ah, const __nv_bfloat16* __restrict__ Al,
          const __nv_bfloat16* __restrict__ Bh, const __nv_bfloat16* __restrict__ Bl,
          const float* __restrict__ bias, const float* __restrict__ res,
          float* __restrict__ Cf, __nv_bfloat16* __restrict__ Ch, __nv_bfloat16* __restrict__ Cl,
          int Nc, float* __restrict__ qd, float* __restrict__ kd, float* __restrict__ vd) {
    extern __shared__ char smem[];
    const uint32_t su = smem_to_u32(smem);
    const int tid = threadIdx.x;
    const int wid = tid >> 5, lane = tid & 31;
    const int m0 = blockIdx.y * 128, n0 = blockIdx.x * 64;

    const int wm = (wid & 3) * 32;       // warp row offset in 128
    const int wn = (wid >> 2) * 32;      // warp col offset in 64

    // ldmatrix lane offsets
    const uint32_t laneA = (uint32_t)((((lane >> 3) & 1) * 8 + (lane & 7)) * GSTRIDE + (lane >> 4) * 16);
    const uint32_t laneB = (uint32_t)((((lane >> 4) & 1) * 8 + (lane & 7)) * GSTRIDE + ((lane >> 3) & 1) * 16);

    // cp.async source/dst mapping
    const int arow = tid >> 1;                   // 0..127 (2 chunk-cols per thread pass)
    const int acp0 = (tid & 1) * 2;              // chunk col 0/2
    const int brow = tid >> 2;                   // 0..63
    const int bcp = tid & 3;

    float c[2][4][4];
#pragma unroll
    for (int mi = 0; mi < 2; mi++)
#pragma unroll
        for (int nt = 0; nt < 4; nt++)
#pragma unroll
            for (int e = 0; e < 4; e++) c[mi][nt][e] = 0.f;

    auto issue_stage = [&](int s) {
        const int k0 = s * 32;
        const uint32_t bufo = su + (uint32_t)((s & 1) * BUF_SZ);
        const __nv_bfloat16* gAh = Ah + (size_t)(m0 + arow) * 512 + k0 + acp0 * 8;
        const __nv_bfloat16* gAl = Al + (size_t)(m0 + arow) * 512 + k0 + acp0 * 8;
        uint32_t dA = bufo + (uint32_t)(arow * GSTRIDE + acp0 * 16);
        CP_ASYNC16(dA + OFF_AH, gAh);
        CP_ASYNC16(dA + OFF_AH + 16, gAh + 8);
        CP_ASYNC16(dA + OFF_AL, gAl);
        CP_ASYNC16(dA + OFF_AL + 16, gAl + 8);
        if (tid < 256) {
            const __nv_bfloat16* gBh = Bh + (size_t)(n0 + brow) * 512 + k0 + bcp * 8;
            const __nv_bfloat16* gBl = Bl + (size_t)(n0 + brow) * 512 + k0 + bcp * 8;
            uint32_t dB = bufo + (uint32_t)(brow * GSTRIDE + bcp * 16);
            CP_ASYNC16(dB + OFF_BH, gBh);
            CP_ASYNC16(dB + OFF_BL, gBl);
        }
    };

    issue_stage(0);
    CP_COMMIT();

    for (int s = 0; s < 16; s++) {
        if (s + 1 < 16) {
            issue_stage(s + 1);
            CP_COMMIT();
            CP_WAIT(1);
        } else {
            CP_WAIT(0);
        }
        __syncthreads();
        const uint32_t bufo = su + (uint32_t)((s & 1) * BUF_SZ);
#pragma unroll
        for (int ks = 0; ks < 2; ks++) {
            uint32_t ah[2][4], al[2][4], bh[2][4], bl[2][4];
#pragma unroll
            for (int mi = 0; mi < 2; mi++) {
                uint32_t aaddr = bufo + (uint32_t)((wm + mi * 16) * GSTRIDE + ks * 32) + laneA;
                LDSM_X4(ah[mi], aaddr + OFF_AH);
                LDSM_X4(al[mi], aaddr + OFF_AL);
            }
#pragma unroll
            for (int ni = 0; ni < 2; ni++) {
                uint32_t baddr = bufo + (uint32_t)((wn + ni * 16) * GSTRIDE + ks * 32) + laneB;
                LDSM_X4(bh[ni], baddr + OFF_BH);
                LDSM_X4(bl[ni], baddr + OFF_BL);
            }
#pragma unroll
            for (int mi = 0; mi < 2; mi++)
#pragma unroll
                for (int nt = 0; nt < 4; nt++) {
                    int ni = nt >> 1, sel = (nt & 1) * 2;
                    mma_bf16(c[mi][nt], ah[mi], bh[ni][sel], bh[ni][sel + 1]);
                    mma_bf16(c[mi][nt], ah[mi], bl[ni][sel], bl[ni][sel + 1]);
                    mma_bf16(c[mi][nt], al[mi], bh[ni][sel], bh[ni][sel + 1]);
                }
        }
        __syncthreads();
    }

    // -------- epilogue --------
#pragma unroll
    for (int mi = 0; mi < 2; mi++)
#pragma unroll
        for (int nt = 0; nt < 4; nt++) {
#pragma unroll
            for (int hh = 0; hh < 2; hh++) {
                int m = m0 + wm + mi * 16 + (lane >> 2) + hh * 8;
                int cg = n0 + wn + nt * 8 + (lane & 3) * 2;
                float v0 = c[mi][nt][hh * 2 + 0] + __ldg(&bias[cg]);
                float v1 = c[mi][nt][hh * 2 + 1] + __ldg(&bias[cg + 1]);
                if (MODE == 0) {
                    int mat = cg >> 9, rem = cg & 511, n = rem >> 6, d = rem & 63;
                    float* dst = (mat == 0) ? qd : ((mat == 1) ? kd : vd);
                    int bI = m >> 11, l = m & 2047;
                    float* p = &dst[((bI * 8 + n) * 2048 + l) * 64 + d];
                    p[0] = v0; p[1] = v1;
                } else if (MODE == 1) {
                    int n = cg >> 6, d = cg & 63;
                    float* p = &Cf[(n * 2048 + m) * 64 + d];
                    p[0] = v0; p[1] = v1;
                } else if (MODE == 2) {
                    size_t o = (size_t)m * Nc + cg;
                    Cf[o] = v0 + res[o];
                    Cf[o + 1] = v1 + res[o + 1];
                } else {
                    float g0 = gelu_f(v0), g1 = gelu_f(v1);
                    __nv_bfloat16 h0, l0, h1, l1;
                    split_bf16(g0, h0, l0);
                    split_bf16(g1, h1, l1);
                    size_t o = (size_t)m * 512 + cg;
                    Ch[o] = h0; Ch[o + 1] = h1;
                    Cl[o] = l0; Cl[o + 1] = l1;
                }
            }
        }
}

// ================= fused causal rel-pos flash attention (f32x2) =================
#define ATTN_SMEM_BYTES ((4 * 64 * 68 + 64 * 132 + 128) * 4)

__global__ void attn_kernel(const float* __restrict__ qg, const float* __restrict__ kg,
                            const float* __restrict__ vg, const float* __restrict__ rg,
                            const float* __restrict__ cb, const float* __restrict__ pwg,
                            __nv_bfloat16* __restrict__ outh, __nv_bfloat16* __restrict__ outl) {
    extern __shared__ float sm[];
    float* Qcs = sm;
    float* Kst = sm + 4352;
    float* Vs  = sm + 2 * 4352;
    float* Ss  = sm + 3 * 4352;
    float* Rst = sm + 4 * 4352;
    float* pws = sm + 4 * 4352 + 8448;

    const int tid = threadIdx.x;
    const int tx = tid & 15, ty = tid >> 4;
    const int ib = blockIdx.x, bn = blockIdx.y;
    const int n = bn & 7, b = bn >> 3;
    const int I0 = ib * 64;

    const int lrow = tid >> 4;
    const int ld0 = (tid & 15) * 4;

    const float* qbase = qg + (bn * L_ + I0) * D_;
    float4 cbv = *(const float4*)&cb[n * 64 + ld0];
#pragma unroll
    for (int t = 0; t < 4; t++) {
        int rr = lrow + t * 16;
        float4 qv = *(const float4*)&qbase[rr * 64 + ld0];
        float* dst = &Qcs[rr * 68 + ld0];
        dst[0] = qv.x + cbv.x;
        dst[1] = qv.y + cbv.y;
        dst[2] = qv.z + cbv.z;
        dst[3] = qv.w + cbv.w;
    }

    float mrow[4], lsum[4];
    ull o2[4][2];
#pragma unroll
    for (int r = 0; r < 4; r++) {
        mrow[r] = -1e30f; lsum[r] = 0.f;
        o2[r][0] = 0ULL; o2[r][1] = 0ULL;
    }

    const int r0 = ty * 4, c0 = tx * 4;
    const int wbase = 60 - r0 + c0;

    for (int jb = 0; jb <= ib; jb++) {
        __syncthreads();
        const int J0 = jb * 64;
        const int pmin = L_ - 64 - I0 + J0;
        const float* kbase = kg + (bn * L_ + J0) * D_;
        const float* vbase = vg + (bn * L_ + J0) * D_;
#pragma unroll
        for (int t = 0; t < 4; t++) {
            int j = lrow + t * 16;
            float4 kv = *(const float4*)&kbase[j * 64 + ld0];
            Kst[(ld0 + 0) * 68 + j] = kv.x;
            Kst[(ld0 + 1) * 68 + j] = kv.y;
            Kst[(ld0 + 2) * 68 + j] = kv.z;
            Kst[(ld0 + 3) * 68 + j] = kv.w;
            *(float4*)&Vs[j * 68 + ld0] = *(const float4*)&vbase[j * 64 + ld0];
        }
        const float* rbase = rg + n * (L_ * D_);
#pragma unroll
        for (int t = 0; t < 8; t++) {
            int pp = lrow + t * 16;
            int p = pmin + pp;
            float4 rv = make_float4(0.f, 0.f, 0.f, 0.f);
            if (p < L_) rv = *(const float4*)&rbase[p * 64 + ld0];
            Rst[(ld0 + 0) * 132 + pp] = rv.x;
            Rst[(ld0 + 1) * 132 + pp] = rv.y;
            Rst[(ld0 + 2) * 132 + pp] = rv.z;
            Rst[(ld0 + 3) * 132 + pp] = rv.w;
        }
        if (tid < 128) {
            int p = pmin + tid;
            pws[tid] = (p < L_) ? pwg[n * 2048 + p] : 0.f;
        }
        __syncthreads();

        ull s2[4][2];
#pragma unroll
        for (int r = 0; r < 4; r++) { s2[r][0] = 0ULL; s2[r][1] = 0ULL; }

#pragma unroll 4
        for (int kk = 0; kk < 64; kk++) {
            ull a2[4];
#pragma unroll
            for (int r = 0; r < 4; r++) {
                float aq = Qcs[(r0 + r) * 68 + kk];
                a2[r] = pack2f(aq, aq);
            }
            ulonglong2 kb = *(const ulonglong2*)&Kst[kk * 68 + c0];
            float4 w0 = *(const float4*)&Rst[kk * 132 + wbase];
            float4 w1 = *(const float4*)&Rst[kk * 132 + wbase + 4];
            ull p01 = pack2f(w0.x, w0.y), p12 = pack2f(w0.y, w0.z);
            ull p23 = pack2f(w0.z, w0.w), p34 = pack2f(w0.w, w1.x);
            ull p45 = pack2f(w1.x, w1.y), p56 = pack2f(w1.y, w1.z);
            s2[3][0] = fma2f(a2[3], kb.x, s2[3][0]); s2[3][1] = fma2f(a2[3], kb.y, s2[3][1]);
            s2[3][0] = fma2f(a2[3], p01, s2[3][0]);  s2[3][1] = fma2f(a2[3], p23, s2[3][1]);
            s2[2][0] = fma2f(a2[2], kb.x, s2[2][0]); s2[2][1] = fma2f(a2[2], kb.y, s2[2][1]);
            s2[2][0] = fma2f(a2[2], p12, s2[2][0]);  s2[2][1] = fma2f(a2[2], p34, s2[2][1]);
            s2[1][0] = fma2f(a2[1], kb.x, s2[1][0]); s2[1][1] = fma2f(a2[1], kb.y, s2[1][1]);
            s2[1][0] = fma2f(a2[1], p23, s2[1][0]);  s2[1][1] = fma2f(a2[1], p45, s2[1][1]);
            s2[0][0] = fma2f(a2[0], kb.x, s2[0][0]); s2[0][1] = fma2f(a2[0], kb.y, s2[0][1]);
            s2[0][0] = fma2f(a2[0], p34, s2[0][0]);  s2[0][1] = fma2f(a2[0], p56, s2[0][1]);
        }

        float s[4][4];
#pragma unroll
        for (int r = 0; r < 4; r++) {
            unpack2f(s2[r][0], s[r][0], s[r][1]);
            unpack2f(s2[r][1], s[r][2], s[r][3]);
        }
        const bool diag = (jb == ib);
#pragma unroll
        for (int r = 0; r < 4; r++)
#pragma unroll
            for (int c = 0; c < 4; c++) {
                s[r][c] = (s[r][c] + pws[wbase + 3 - r + c]) * 0.125f;
                if (diag && (J0 + c0 + c) > (I0 + r0 + r)) s[r][c] = -1e30f;
            }

#pragma unroll
        for (int r = 0; r < 4; r++) {
            float rm = fmaxf(fmaxf(s[r][0], s[r][1]), fmaxf(s[r][2], s[r][3]));
#pragma unroll
            for (int mk = 8; mk >= 1; mk >>= 1)
                rm = fmaxf(rm, __shfl_xor_sync(0xffffffffu, rm, mk));
            float mn = fmaxf(mrow[r], rm);
            float alpha = __expf(mrow[r] - mn);
            mrow[r] = mn;
            float rs = 0.f;
#pragma unroll
            for (int c = 0; c < 4; c++) {
                s[r][c] = __expf(s[r][c] - mn);
                rs += s[r][c];
            }
#pragma unroll
            for (int mk = 8; mk >= 1; mk >>= 1)
                rs += __shfl_xor_sync(0xffffffffu, rs, mk);
            lsum[r] = lsum[r] * alpha + rs;
            ull al2 = pack2f(alpha, alpha);
            o2[r][0] = mul2f(o2[r][0], al2);
            o2[r][1] = mul2f(o2[r][1], al2);
        }

#pragma unroll
        for (int r = 0; r < 4; r++)
            *(float4*)&Ss[(r0 + r) * 68 + c0] = make_float4(s[r][0], s[r][1], s[r][2], s[r][3]);
        __syncthreads();

#pragma unroll 4
        for (int jj = 0; jj < 64; jj++) {
            ull a2[4];
#pragma unroll
            for (int r = 0; r < 4; r++) {
                float av = Ss[(r0 + r) * 68 + jj];
                a2[r] = pack2f(av, av);
            }
            ulonglong2 bv = *(const ulonglong2*)&Vs[jj * 68 + c0];
#pragma unroll
            for (int r = 0; r < 4; r++) {
                o2[r][0] = fma2f(a2[r], bv.x, o2[r][0]);
                o2[r][1] = fma2f(a2[r], bv.y, o2[r][1]);
            }
        }
    }

#pragma unroll
    for (int r = 0; r < 4; r++) {
        float inv = 1.0f / lsum[r];
        float ov[4];
        unpack2f(o2[r][0], ov[0], ov[1]);
        unpack2f(o2[r][1], ov[2], ov[3]);
        size_t base = (size_t)(b * L_ + I0 + r0 + r) * H_ + n * 64 + c0;
        __nv_bfloat16 hs[4], ls[4];
#pragma unroll
        for (int c = 0; c < 4; c++) split_bf16(ov[c] * inv, hs[c], ls[c]);
        *(ull*)&outh[base] = *(const ull*)hs;
        *(ull*)&outl[base] = *(const ull*)ls;
    }
}

// ================= layernorm (eps=1e-12) =================
template <bool SPLIT>
__global__ void ln_kernel(const float* __restrict__ in, const float* __restrict__ w,
                          const float* __restrict__ bparm, float* __restrict__ out,
                          __nv_bfloat16* __restrict__ oh, __nv_bfloat16* __restrict__ ol) {
    __shared__ float red[8];
    __shared__ float stat[2];
    int row = blockIdx.x, tid = threadIdx.x;
    const float* xr = in + (size_t)row * H_;
    float v0 = xr[tid], v1 = xr[tid + 256];
    float s = v0 + v1;
#pragma unroll
    for (int mk = 16; mk >= 1; mk >>= 1) s += __shfl_xor_sync(0xffffffffu, s, mk);
    if ((tid & 31) == 0) red[tid >> 5] = s;
    __syncthreads();
    if (tid == 0) {
        float t = 0;
#pragma unroll
        for (int i = 0; i < 8; i++) t += red[i];
        stat[0] = t * (1.0f / H_);
    }
    __syncthreads();
    float u = stat[0];
    float d0 = v0 - u, d1 = v1 - u;
    float q = d0 * d0 + d1 * d1;
#pragma unroll
    for (int mk = 16; mk >= 1; mk >>= 1) q += __shfl_xor_sync(0xffffffffu, q, mk);
    __syncthreads();
    if ((tid & 31) == 0) red[tid >> 5] = q;
    __syncthreads();
    if (tid == 0) {
        float t = 0;
#pragma unroll
        for (int i = 0; i < 8; i++) t += red[i];
        stat[1] = rsqrtf(t * (1.0f / H_) + 1e-12f);
    }
    __syncthreads();
    float inv = stat[1];
    float r0v = w[tid] * d0 * inv + bparm[tid];
    float r1v = w[tid + 256] * d1 * inv + bparm[tid + 256];
    out[(size_t)row * H_ + tid] = r0v;
    out[(size_t)row * H_ + tid + 256] = r1v;
    if (SPLIT) {
        __nv_bfloat16 h, l;
        split_bf16(r0v, h, l);
        oh[(size_t)row * H_ + tid] = h; ol[(size_t)row * H_ + tid] = l;
        split_bf16(r1v, h, l);
        oh[(size_t)row * H_ + tid + 256] = h; ol[(size_t)row * H_ + tid + 256] = l;
    }
}

// ================= launch =================
extern "C" void kernel_launch(void* const* d_in, const int* in_sizes, int n_in,
                              void* d_out, int out_size) {
    (void)in_sizes; (void)n_in; (void)out_size;
    const float* x  = (const float*)d_in[0];
    const float* pe = (const float*)d_in[1];
    const float* Wq = (const float*)d_in[2];
    const float* bq = (const float*)d_in[3];
    const float* Wk = (const float*)d_in[4];
    const float* bk = (const float*)d_in[5];
    const float* Wv = (const float*)d_in[6];
    const float* bv = (const float*)d_in[7];
    const float* Wr = (const float*)d_in[8];
    const float* br = (const float*)d_in[9];
    const float* cb = (const float*)d_in[10];
    const float* pb = (const float*)d_in[11];
    const float* Wc = (const float*)d_in[12];
    const float* bc = (const float*)d_in[13];
    const float* W1 = (const float*)d_in[14];
    const float* b1 = (const float*)d_in[15];
    const float* W2 = (const float*)d_in[16];
    const float* b2 = (const float*)d_in[17];
    const float* lnw = (const float*)d_in[18];
    const float* lnb = (const float*)d_in[19];
    float* out = (float*)d_out;

    __nv_bfloat16 *pxh, *pxl, *ppeh, *ppel, *pBqh, *pBql, *pBrh, *pBrl;
    __nv_bfloat16 *pWch, *pWcl, *pW1h, *pW1l, *pW2h, *pW2l;
    __nv_bfloat16 *path, *patl, *pah, *pal, *ph1h, *ph1l;
    float *pbqkv, *pbrp, *pq, *pk, *pv, *pr, *ppw, *py1, *pa, *py2;
    cudaGetSymbolAddress((void**)&pxh, g_xh);
    cudaGetSymbolAddress((void**)&pxl, g_xl);
    cudaGetSymbolAddress((void**)&ppeh, g_peh);
    cudaGetSymbolAddress((void**)&ppel, g_pel);
    cudaGetSymbolAddress((void**)&pBqh, g_Bqkvh);
    cudaGetSymbolAddress((void**)&pBql, g_Bqkvl);
    cudaGetSymbolAddress((void**)&pBrh, g_Brh);
    cudaGetSymbolAddress((void**)&pBrl, g_Brl);
    cudaGetSymbolAddress((void**)&pWch, g_Wch);
    cudaGetSymbolAddress((void**)&pWcl, g_Wcl);
    cudaGetSymbolAddress((void**)&pW1h, g_W1h);
    cudaGetSymbolAddress((void**)&pW1l, g_W1l);
    cudaGetSymbolAddress((void**)&pW2h, g_W2h);
    cudaGetSymbolAddress((void**)&pW2l, g_W2l);
    cudaGetSymbolAddress((void**)&path, g_attnh);
    cudaGetSymbolAddress((void**)&patl, g_attnl);
    cudaGetSymbolAddress((void**)&pah, g_ah);
    cudaGetSymbolAddress((void**)&pal, g_al);
    cudaGetSymbolAddress((void**)&ph1h, g_h1h);
    cudaGetSymbolAddress((void**)&ph1l, g_h1l);
    cudaGetSymbolAddress((void**)&pbqkv, g_bqkv);
    cudaGetSymbolAddress((void**)&pbrp, g_brp);
    cudaGetSymbolAddress((void**)&pq, g_q);
    cudaGetSymbolAddress((void**)&pk, g_k);
    cudaGetSymbolAddress((void**)&pv, g_v);
    cudaGetSymbolAddress((void**)&pr, g_rb);
    cudaGetSymbolAddress((void**)&ppw, g_pw);
    cudaGetSymbolAddress((void**)&py1, g_y1);
    cudaGetSymbolAddress((void**)&pa, g_a);
    cudaGetSymbolAddress((void**)&py2, g_y2);

    cudaFuncSetAttribute(attn_kernel, cudaFuncAttributeMaxDynamicSharedMemorySize, ATTN_SMEM_BYTES);
    cudaFuncSetAttribute(gemm_hmma<0>, cudaFuncAttributeMaxDynamicSharedMemorySize, HMMA_SMEM);
    cudaFuncSetAttribute(gemm_hmma<1>, cudaFuncAttributeMaxDynamicSharedMemorySize, HMMA_SMEM);
    cudaFuncSetAttribute(gemm_hmma<2>, cudaFuncAttributeMaxDynamicSharedMemorySize, HMMA_SMEM);
    cudaFuncSetAttribute(gemm_hmma<3>, cudaFuncAttributeMaxDynamicSharedMemorySize, HMMA_SMEM);

    // converts + packs
    conv_split<<<2048, 256>>>(x, pxh, pxl, B_ * L_ * H_);
    conv_split<<<1024, 256>>>(pe, ppeh, ppel, L_ * H_);
    conv_split<<<512, 256>>>(Wc, pWch, pWcl, H_ * H_);
    conv_split<<<512, 256>>>(W1, pW1h, pW1l, H_ * H_);
    conv_split<<<512, 256>>>(W2, pW2h, pW2l, H_ * H_);
    pack_qkvr<<<768, 256>>>(Wq, bq, Wk, bk, Wv, bv, Wr, br);

    // QKV: (8192x512)@(1536x512)^T -> scatter q/k/v
    gemm_hmma<0><<<dim3(24, 64), 256, HMMA_SMEM>>>(
        pxh, pxl, pBqh, pBql, pbqkv, nullptr, nullptr, nullptr, nullptr, 1536, pq, pk, pv);

    // R: (2048x512)@(512x512)^T -> r scatter
    gemm_hmma<1><<<dim3(8, 16), 256, HMMA_SMEM>>>(
        ppeh, ppel, pBrh, pBrl, pbrp, nullptr, pr, nullptr, nullptr, 512, nullptr, nullptr, nullptr);

    pw_kernel<<<dim3(16, 8), 128>>>(cb, pb, ppw);

    attn_kernel<<<dim3(L_ / 64, B_ * N_), 256, ATTN_SMEM_BYTES>>>(pq, pk, pv, pr, cb, ppw, path, patl);

    // Wc + residual(x) -> y1
    gemm_hmma<2><<<dim3(8, 64), 256, HMMA_SMEM>>>(
        path, patl, pWch, pWcl, bc, x, py1, nullptr, nullptr, 512, nullptr, nullptr, nullptr);

    ln_kernel<true><<<B_ * L_, 256>>>(py1, lnw, lnb, pa, pah, pal);

    // FFN up + GELU -> h1 planes
    gemm_hmma<3><<<dim3(8, 64), 256, HMMA_SMEM>>>(
        pah, pal, pW1h, pW1l, b1, nullptr, nullptr, ph1h, ph1l, 512, nullptr, nullptr, nullptr);

    // FFN down + residual(a) -> y2
    gemm_hmma<2><<<dim3(8, 64), 256, HMMA_SMEM>>>(
        ph1h, ph1l, pW2h, pW2l, b2, pa, py2, nullptr, nullptr, 512, nullptr, nullptr, nullptr);

    ln_kernel<false><<<B_ * L_, 256>>>(py2, lnw, lnb, out, nullptr, nullptr);
}

// round 10
// speedup vs baseline: 2.0332x; 1.5368x over previous
#include <cuda_runtime.h>
#include <cuda_bf16.h>
#include <cuda_fp16.h>
#include <math.h>
#include <stdint.h>

#define B_ 4
#define L_ 2048
#define H_ 512
#define N_ 8
#define D_ 64

typedef unsigned long long ull;

// ================= common helpers =================
__device__ __forceinline__ uint32_t smem_to_u32(const void* p) {
    uint32_t a;
    asm("{ .reg .u64 t; cvta.to.shared.u64 t, %1; cvt.u32.u64 %0, t; }" : "=r"(a) : "l"(p));
    return a;
}

#define LDSM_X4(r, addr)                                                          \
    asm volatile("ldmatrix.sync.aligned.m8n8.x4.shared.b16 {%0,%1,%2,%3}, [%4];"  \
        : "=r"((r)[0]), "=r"((r)[1]), "=r"((r)[2]), "=r"((r)[3]) : "r"(addr))

#define LDSM_X4_T(r, addr)                                                              \
    asm volatile("ldmatrix.sync.aligned.m8n8.x4.trans.shared.b16 {%0,%1,%2,%3}, [%4];"  \
        : "=r"((r)[0]), "=r"((r)[1]), "=r"((r)[2]), "=r"((r)[3]) : "r"(addr))

__device__ __forceinline__ void mma_bf16(float* c, const uint32_t* a, uint32_t b0, uint32_t b1) {
    asm volatile(
        "mma.sync.aligned.m16n8k16.row.col.f32.bf16.bf16.f32 "
        "{%0,%1,%2,%3}, {%4,%5,%6,%7}, {%8,%9}, {%0,%1,%2,%3};"
        : "+f"(c[0]), "+f"(c[1]), "+f"(c[2]), "+f"(c[3])
        : "r"(a[0]), "r"(a[1]), "r"(a[2]), "r"(a[3]), "r"(b0), "r"(b1));
}

#define CP_ASYNC16(dst, src) asm volatile("cp.async.cg.shared.global [%0], [%1], 16;" :: "r"(dst), "l"(src))
#define CP_COMMIT()          asm volatile("cp.async.commit_group;" ::: "memory")
#define CP_WAIT(n)           asm volatile("cp.async.wait_group %0;" :: "n"(n) : "memory")

// ================= scratch =================
__device__ __nv_bfloat16 g_xh[B_ * L_ * H_];
__device__ __nv_bfloat16 g_xl[B_ * L_ * H_];
__device__ __nv_bfloat16 g_peh[L_ * H_];
__device__ __nv_bfloat16 g_pel[L_ * H_];
__device__ __nv_bfloat16 g_Bqkvh[3 * H_ * H_];
__device__ __nv_bfloat16 g_Bqkvl[3 * H_ * H_];
__device__ __nv_bfloat16 g_Brh[H_ * H_];
__device__ __nv_bfloat16 g_Brl[H_ * H_];
__device__ __nv_bfloat16 g_Wch[H_ * H_];
__device__ __nv_bfloat16 g_Wcl[H_ * H_];
__device__ __nv_bfloat16 g_W1h[H_ * H_];
__device__ __nv_bfloat16 g_W1l[H_ * H_];
__device__ __nv_bfloat16 g_W2h[H_ * H_];
__device__ __nv_bfloat16 g_W2l[H_ * H_];
__device__ float g_bqkv[3 * H_];
__device__ float g_brp[H_];
// attention operand planes (bf16 hi/lo)
__device__ __nv_bfloat16 g_qh[32 * L_ * D_];
__device__ __nv_bfloat16 g_ql[32 * L_ * D_];
__device__ __nv_bfloat16 g_kh[32 * L_ * D_];
__device__ __nv_bfloat16 g_kl[32 * L_ * D_];
__device__ __nv_bfloat16 g_vh[32 * L_ * D_];
__device__ __nv_bfloat16 g_vl[32 * L_ * D_];
__device__ __nv_bfloat16 g_rh[N_ * L_ * D_];
__device__ __nv_bfloat16 g_rl[N_ * L_ * D_];
__device__ float g_rb[N_ * L_ * D_];
__device__ float g_pw[N_ * L_];
__device__ __nv_bfloat16 g_attnh[B_ * L_ * H_];
__device__ __nv_bfloat16 g_attnl[B_ * L_ * H_];
__device__ float g_y1[B_ * L_ * H_];
__device__ float g_a[B_ * L_ * H_];
__device__ __nv_bfloat16 g_ah[B_ * L_ * H_];
__device__ __nv_bfloat16 g_al[B_ * L_ * H_];
__device__ __nv_bfloat16 g_h1h[B_ * L_ * H_];
__device__ __nv_bfloat16 g_h1l[B_ * L_ * H_];
__device__ float g_y2[B_ * L_ * H_];

// ================= split-convert =================
__device__ __forceinline__ void split_bf16(float v, __nv_bfloat16& h, __nv_bfloat16& l) {
    h = __float2bfloat16(v);
    l = __float2bfloat16(v - __bfloat162float(h));
}

__global__ void conv_split(const float* __restrict__ src, __nv_bfloat16* __restrict__ dh,
                           __nv_bfloat16* __restrict__ dl, int n) {
    int i = blockIdx.x * 256 + threadIdx.x;
    int stride = gridDim.x * 256;
    for (; i < n; i += stride) {
        __nv_bfloat16 h, l;
        split_bf16(src[i], h, l);
        dh[i] = h; dl[i] = l;
    }
}

__global__ void pack_qkvr(const float* __restrict__ Wq, const float* __restrict__ bq,
                          const float* __restrict__ Wk, const float* __restrict__ bk,
                          const float* __restrict__ Wv, const float* __restrict__ bv,
                          const float* __restrict__ Wr, const float* __restrict__ br) {
    int idx = blockIdx.x * 256 + threadIdx.x;
    int stride = gridDim.x * 256;
    for (int i = idx; i < 1536 * 512; i += stride) {
        int c = i >> 9, h = i & 511;
        int mat = c >> 9, rem = c & 511, n = rem >> 6, d = rem & 63;
        const float* W = (mat == 0) ? Wq : ((mat == 1) ? Wk : Wv);
        __nv_bfloat16 hh, ll;
        split_bf16(W[(n * 512 + h) * 64 + d], hh, ll);
        g_Bqkvh[i] = hh; g_Bqkvl[i] = ll;
    }
    for (int i = idx; i < 512 * 512; i += stride) {
        int c = i >> 9, h = i & 511;
        int n = c >> 6, d = c & 63;
        __nv_bfloat16 hh, ll;
        split_bf16(Wr[(n * 512 + h) * 64 + d], hh, ll);
        g_Brh[i] = hh; g_Brl[i] = ll;
    }
    for (int i = idx; i < 1536; i += stride) {
        int mat = i >> 9, rem = i & 511;
        const float* bb = (mat == 0) ? bq : ((mat == 1) ? bk : bv);
        g_bqkv[i] = bb[rem];
    }
    for (int i = idx; i < 512; i += stride) g_brp[i] = br[i];
}

__global__ void pw_kernel(const float* __restrict__ cb, const float* __restrict__ pb,
                          float* __restrict__ pwg) {
    int n = blockIdx.y;
    int p = blockIdx.x * 128 + threadIdx.x;
    const float* rp = &g_rb[(n * 2048 + p) * 64];
    float s = 0.f;
#pragma unroll 16
    for (int d = 0; d < 64; d++) s += (pb[n * 64 + d] - cb[n * 64 + d]) * rp[d];
    pwg[n * 2048 + p] = s;
}

__device__ __forceinline__ float gelu_f(float v) {
    return 0.5f * v * (1.0f + erff(v * 0.70710678118654752f));
}

// ================= HMMA GEMM (as in R9): 128x64 block, 8 warps 32x32, K=512 =================
// MODE 0: qkv scatter -> split planes (+cb on q via res)   MODE 1: r scatter -> float + planes
// MODE 2: Cf = acc + bias + res                            MODE 3: gelu(acc+bias) -> Ch/Cl
#define GSTRIDE 80
#define OFF_AH 0
#define OFF_AL 10240
#define OFF_BH 20480
#define OFF_BL 25600
#define BUF_SZ 30720
#define HMMA_SMEM (2 * BUF_SZ + 128)

template <int MODE>
__global__ void __launch_bounds__(256, 2)
gemm_hmma(const __nv_bfloat16* __restrict__ Ah, const __nv_bfloat16* __restrict__ Al,
          const __nv_bfloat16* __restrict__ Bh, const __nv_bfloat16* __restrict__ Bl,
          const float* __restrict__ bias, const float* __restrict__ res,
          float* __restrict__ Cf, __nv_bfloat16* __restrict__ Ch, __nv_bfloat16* __restrict__ Cl,
          int Nc) {
    extern __shared__ char smem[];
    const uint32_t su = smem_to_u32(smem);
    const int tid = threadIdx.x;
    const int wid = tid >> 5, lane = tid & 31;
    const int m0 = blockIdx.y * 128, n0 = blockIdx.x * 64;

    const int wm = (wid & 3) * 32;
    const int wn = (wid >> 2) * 32;

    const uint32_t laneA = (uint32_t)((((lane >> 3) & 1) * 8 + (lane & 7)) * GSTRIDE + (lane >> 4) * 16);
    const uint32_t laneB = (uint32_t)((((lane >> 4) & 1) * 8 + (lane & 7)) * GSTRIDE + ((lane >> 3) & 1) * 16);

    const int arow = tid >> 1;
    const int acp0 = (tid & 1) * 2;
    const int brow = tid >> 2;
    const int bcp = tid & 3;

    float c[2][4][4];
#pragma unroll
    for (int mi = 0; mi < 2; mi++)
#pragma unroll
        for (int nt = 0; nt < 4; nt++)
#pragma unroll
            for (int e = 0; e < 4; e++) c[mi][nt][e] = 0.f;

    auto issue_stage = [&](int s) {
        const int k0 = s * 32;
        const uint32_t bufo = su + (uint32_t)((s & 1) * BUF_SZ);
        const __nv_bfloat16* gAh = Ah + (size_t)(m0 + arow) * 512 + k0 + acp0 * 8;
        const __nv_bfloat16* gAl = Al + (size_t)(m0 + arow) * 512 + k0 + acp0 * 8;
        uint32_t dA = bufo + (uint32_t)(arow * GSTRIDE + acp0 * 16);
        CP_ASYNC16(dA + OFF_AH, gAh);
        CP_ASYNC16(dA + OFF_AH + 16, gAh + 8);
        CP_ASYNC16(dA + OFF_AL, gAl);
        CP_ASYNC16(dA + OFF_AL + 16, gAl + 8);
        {
            const __nv_bfloat16* gBh = Bh + (size_t)(n0 + brow) * 512 + k0 + bcp * 8;
            const __nv_bfloat16* gBl = Bl + (size_t)(n0 + brow) * 512 + k0 + bcp * 8;
            uint32_t dB = bufo + (uint32_t)(brow * GSTRIDE + bcp * 16);
            CP_ASYNC16(dB + OFF_BH, gBh);
            CP_ASYNC16(dB + OFF_BL, gBl);
        }
    };

    issue_stage(0);
    CP_COMMIT();

    for (int s = 0; s < 16; s++) {
        if (s + 1 < 16) {
            issue_stage(s + 1);
            CP_COMMIT();
            CP_WAIT(1);
        } else {
            CP_WAIT(0);
        }
        __syncthreads();
        const uint32_t bufo = su + (uint32_t)((s & 1) * BUF_SZ);
#pragma unroll
        for (int ks = 0; ks < 2; ks++) {
            uint32_t ah[2][4], al[2][4], bh[2][4], bl[2][4];
#pragma unroll
            for (int mi = 0; mi < 2; mi++) {
                uint32_t aaddr = bufo + (uint32_t)((wm + mi * 16) * GSTRIDE + ks * 32) + laneA;
                LDSM_X4(ah[mi], aaddr + OFF_AH);
                LDSM_X4(al[mi], aaddr + OFF_AL);
            }
#pragma unroll
            for (int ni = 0; ni < 2; ni++) {
                uint32_t baddr = bufo + (uint32_t)((wn + ni * 16) * GSTRIDE + ks * 32) + laneB;
                LDSM_X4(bh[ni], baddr + OFF_BH);
                LDSM_X4(bl[ni], baddr + OFF_BL);
            }
#pragma unroll
            for (int mi = 0; mi < 2; mi++)
#pragma unroll
                for (int nt = 0; nt < 4; nt++) {
                    int ni = nt >> 1, sel = (nt & 1) * 2;
                    mma_bf16(c[mi][nt], ah[mi], bh[ni][sel], bh[ni][sel + 1]);
                    mma_bf16(c[mi][nt], ah[mi], bl[ni][sel], bl[ni][sel + 1]);
                    mma_bf16(c[mi][nt], al[mi], bh[ni][sel], bh[ni][sel + 1]);
                }
        }
        __syncthreads();
    }

    // -------- epilogue --------
#pragma unroll
    for (int mi = 0; mi < 2; mi++)
#pragma unroll
        for (int nt = 0; nt < 4; nt++) {
#pragma unroll
            for (int hh = 0; hh < 2; hh++) {
                int m = m0 + wm + mi * 16 + (lane >> 2) + hh * 8;
                int cg = n0 + wn + nt * 8 + (lane & 3) * 2;
                float v0 = c[mi][nt][hh * 2 + 0] + __ldg(&bias[cg]);
                float v1 = c[mi][nt][hh * 2 + 1] + __ldg(&bias[cg + 1]);
                if (MODE == 0) {
                    int mat = cg >> 9, rem = cg & 511, n2 = rem >> 6, d = rem & 63;
                    int bI = m >> 11, l = m & 2047;
                    size_t o = ((size_t)(bI * 8 + n2) * 2048 + l) * 64 + d;
                    if (mat == 0) { v0 += __ldg(&res[rem]); v1 += __ldg(&res[rem + 1]); }
                    __nv_bfloat16 h0, l0, h1, l1;
                    split_bf16(v0, h0, l0); split_bf16(v1, h1, l1);
                    __nv_bfloat162 th; th.x = h0; th.y = h1;
                    __nv_bfloat162 tl; tl.x = l0; tl.y = l1;
                    if (mat == 0)      { *(__nv_bfloat162*)&g_qh[o] = th; *(__nv_bfloat162*)&g_ql[o] = tl; }
                    else if (mat == 1) { *(__nv_bfloat162*)&g_kh[o] = th; *(__nv_bfloat162*)&g_kl[o] = tl; }
                    else               { *(__nv_bfloat162*)&g_vh[o] = th; *(__nv_bfloat162*)&g_vl[o] = tl; }
                } else if (MODE == 1) {
                    int n2 = cg >> 6, d = cg & 63;
                    size_t o = ((size_t)n2 * 2048 + m) * 64 + d;
                    Cf[o] = v0; Cf[o + 1] = v1;
                    __nv_bfloat16 h0, l0, h1, l1;
                    split_bf16(v0, h0, l0); split_bf16(v1, h1, l1);
                    __nv_bfloat162 th; th.x = h0; th.y = h1;
                    __nv_bfloat162 tl; tl.x = l0; tl.y = l1;
                    *(__nv_bfloat162*)&g_rh[o] = th;
                    *(__nv_bfloat162*)&g_rl[o] = tl;
                } else if (MODE == 2) {
                    size_t o = (size_t)m * Nc + cg;
                    Cf[o] = v0 + res[o];
                    Cf[o + 1] = v1 + res[o + 1];
                } else {
                    float g0 = gelu_f(v0), g1 = gelu_f(v1);
                    __nv_bfloat16 h0, l0, h1, l1;
                    split_bf16(g0, h0, l0); split_bf16(g1, h1, l1);
                    size_t o = (size_t)m * 512 + cg;
                    Ch[o] = h0; Ch[o + 1] = h1;
                    Cl[o] = l0; Cl[o + 1] = l1;
                }
            }
        }
}

// ================= tensor-core flash attention =================
// s[ii][jj] = (qc·k + T[ii][63-ii+jj]) / 8, T = qc·r_window + pw  (pw folded at T store)
// 64 q-rows per CTA, 64-key j-tiles, 8 warps: (wid&3)->16-row group, (wid>>2)->col half.
#define AT_STRB 144                      // 72 bf16 per row
#define AO_QH 0
#define AO_QL 9216
#define AO_KH 18432
#define AO_KL 27648
#define AO_VH 36864
#define AO_VL 46080
#define AO_RH 55296
#define AO_RL 73728
#define AO_PH 92160
#define AO_PL 101376
#define AO_TS 110592
#define AO_PW 145408
#define AO_RM 145920
#define AO_RS 146432
#define ATTN_SMEM2 146944

__global__ void __launch_bounds__(256)
attn_mma() {
    extern __shared__ char sm8[];
    const uint32_t su = smem_to_u32(sm8);
    const int tid = threadIdx.x, wid = tid >> 5, lane = tid & 31;
    const int ib = blockIdx.x, bn = blockIdx.y;
    const int n = bn & 7, b = bn >> 3;
    const int I0 = ib * 64;
    const int wr = (wid & 3) * 16, wc2 = wid >> 2;
    const int rg = lane >> 2, c4 = lane & 3;

    const uint32_t laneA  = (uint32_t)((((lane >> 3) & 1) * 8 + (lane & 7)) * AT_STRB + (lane >> 4) * 16);
    const uint32_t laneB  = (uint32_t)((((lane >> 4) & 1) * 8 + (lane & 7)) * AT_STRB + ((lane >> 3) & 1) * 16);
    const uint32_t laneBT = (uint32_t)((lane & 15) * AT_STRB + (lane >> 4) * 16);

    // load Q (qc planes) once: 64x64 bf16 x2
    {
        const int row = tid >> 2, cb8 = (tid & 3) * 16;
        size_t g = ((size_t)bn * L_ + I0 + row) * 64 + cb8;
        const uint4* s1 = (const uint4*)&g_qh[g];
        const uint4* s2 = (const uint4*)&g_ql[g];
        uint32_t d0 = (uint32_t)(row * AT_STRB + cb8 * 2);
        *(uint4*)(sm8 + AO_QH + d0) = s1[0];
        *(uint4*)(sm8 + AO_QH + d0 + 16) = s1[1];
        *(uint4*)(sm8 + AO_QL + d0) = s2[0];
        *(uint4*)(sm8 + AO_QL + d0 + 16) = s2[1];
    }

    float mrow[2] = {-1e30f, -1e30f};
    float lsum[2] = {0.f, 0.f};
    float o[4][4];
#pragma unroll
    for (int nt = 0; nt < 4; nt++)
#pragma unroll
        for (int e = 0; e < 4; e++) o[nt][e] = 0.f;

    for (int jb = 0; jb <= ib; jb++) {
        const int J0 = jb * 64;
        const int pmin = L_ - 64 - I0 + J0;
        __syncthreads();   // prev-iteration PV reads done
        // ---- loads: K,V (64x64 x2 each), R (128x64 x2), pw (128) ----
        {
            const int row = tid >> 2, cb8 = (tid & 3) * 16;
            uint32_t d0 = (uint32_t)(row * AT_STRB + cb8 * 2);
            size_t gk = ((size_t)bn * L_ + J0 + row) * 64 + cb8;
            const uint4* s1 = (const uint4*)&g_kh[gk];
            const uint4* s2 = (const uint4*)&g_kl[gk];
            const uint4* s3 = (const uint4*)&g_vh[gk];
            const uint4* s4 = (const uint4*)&g_vl[gk];
            *(uint4*)(sm8 + AO_KH + d0) = s1[0]; *(uint4*)(sm8 + AO_KH + d0 + 16) = s1[1];
            *(uint4*)(sm8 + AO_KL + d0) = s2[0]; *(uint4*)(sm8 + AO_KL + d0 + 16) = s2[1];
            *(uint4*)(sm8 + AO_VH + d0) = s3[0]; *(uint4*)(sm8 + AO_VH + d0 + 16) = s3[1];
            *(uint4*)(sm8 + AO_VL + d0) = s4[0]; *(uint4*)(sm8 + AO_VL + d0 + 16) = s4[1];
#pragma unroll
            for (int t = 0; t < 2; t++) {
                int pp = row + t * 64;
                int p = pmin + pp;
                uint32_t dr = (uint32_t)(pp * AT_STRB + cb8 * 2);
                uint4 z = make_uint4(0, 0, 0, 0);
                uint4 r0 = z, r1 = z, r2 = z, r3 = z;
                if (p < L_) {
                    size_t gr = ((size_t)n * L_ + p) * 64 + cb8;
                    const uint4* t1 = (const uint4*)&g_rh[gr];
                    const uint4* t2 = (const uint4*)&g_rl[gr];
                    r0 = t1[0]; r1 = t1[1]; r2 = t2[0]; r3 = t2[1];
                }
                *(uint4*)(sm8 + AO_RH + dr) = r0; *(uint4*)(sm8 + AO_RH + dr + 16) = r1;
                *(uint4*)(sm8 + AO_RL + dr) = r2; *(uint4*)(sm8 + AO_RL + dr + 16) = r3;
            }
            if (tid < 128) {
                int p = pmin + tid;
                *(float*)(sm8 + AO_PW + tid * 4) = (p < L_) ? g_pw[n * 2048 + p] : 0.f;
            }
        }
        __syncthreads();

        // ---- QK (regs) + T (-> Ts smem) ----
        float sQK[4][4], tacc[8][4];
#pragma unroll
        for (int nt = 0; nt < 4; nt++)
#pragma unroll
            for (int e = 0; e < 4; e++) sQK[nt][e] = 0.f;
#pragma unroll
        for (int nt = 0; nt < 8; nt++)
#pragma unroll
            for (int e = 0; e < 4; e++) tacc[nt][e] = 0.f;

#pragma unroll
        for (int ks = 0; ks < 4; ks++) {
            uint32_t ah[4], al[4];
            uint32_t abase = su + (uint32_t)(wr * AT_STRB + ks * 32) + laneA;
            LDSM_X4(ah, abase + AO_QH);
            LDSM_X4(al, abase + AO_QL);
            uint32_t kbh[2][4], kbl[2][4];
#pragma unroll
            for (int f = 0; f < 2; f++) {
                uint32_t baddr = su + (uint32_t)((wc2 * 32 + f * 16) * AT_STRB + ks * 32) + laneB;
                LDSM_X4(kbh[f], baddr + AO_KH);
                LDSM_X4(kbl[f], baddr + AO_KL);
            }
#pragma unroll
            for (int nt = 0; nt < 4; nt++) {
                int f = nt >> 1, sel = (nt & 1) * 2;
                mma_bf16(sQK[nt], ah, kbh[f][sel], kbh[f][sel + 1]);
                mma_bf16(sQK[nt], ah, kbl[f][sel], kbl[f][sel + 1]);
                mma_bf16(sQK[nt], al, kbh[f][sel], kbh[f][sel + 1]);
            }
            uint32_t rbh[4][4], rbl[4][4];
#pragma unroll
            for (int f = 0; f < 4; f++) {
                uint32_t baddr = su + (uint32_t)((wc2 * 64 + f * 16) * AT_STRB + ks * 32) + laneB;
                LDSM_X4(rbh[f], baddr + AO_RH);
                LDSM_X4(rbl[f], baddr + AO_RL);
            }
#pragma unroll
            for (int nt = 0; nt < 8; nt++) {
                int f = nt >> 1, sel = (nt & 1) * 2;
                mma_bf16(tacc[nt], ah, rbh[f][sel], rbh[f][sel + 1]);
                mma_bf16(tacc[nt], ah, rbl[f][sel], rbl[f][sel + 1]);
                mma_bf16(tacc[nt], al, rbh[f][sel], rbh[f][sel + 1]);
            }
        }
        // store T (+pw) to smem
#pragma unroll
        for (int nt = 0; nt < 8; nt++) {
#pragma unroll
            for (int e = 0; e < 4; e++) {
                int row = wr + rg + (e >> 1) * 8;
                int col = wc2 * 64 + nt * 8 + c4 * 2 + (e & 1);
                *(float*)(sm8 + AO_TS + (row * 136 + col) * 4) =
                    tacc[nt][e] + *(float*)(sm8 + AO_PW + col * 4);
            }
        }
        __syncthreads();

        // ---- softmax ----
        const bool diag = (jb == ib);
        float s[4][4];
        float wmax[2] = {-1e30f, -1e30f};
#pragma unroll
        for (int nt = 0; nt < 4; nt++) {
#pragma unroll
            for (int e = 0; e < 4; e++) {
                int ii = wr + rg + (e >> 1) * 8;
                int jj = wc2 * 32 + nt * 8 + c4 * 2 + (e & 1);
                float v = sQK[nt][e] + *(float*)(sm8 + AO_TS + (ii * 136 + (63 - ii + jj)) * 4);
                v *= 0.125f;
                if (diag && jj > ii) v = -1e30f;
                s[nt][e] = v;
                wmax[e >> 1] = fmaxf(wmax[e >> 1], v);
            }
        }
#pragma unroll
        for (int h = 0; h < 2; h++) {
            wmax[h] = fmaxf(wmax[h], __shfl_xor_sync(0xffffffffu, wmax[h], 1));
            wmax[h] = fmaxf(wmax[h], __shfl_xor_sync(0xffffffffu, wmax[h], 2));
        }
        if (c4 == 0) {
            *(float*)(sm8 + AO_RM + (wc2 * 64 + wr + rg) * 4) = wmax[0];
            *(float*)(sm8 + AO_RM + (wc2 * 64 + wr + rg + 8) * 4) = wmax[1];
        }
        __syncthreads();
        float alpha[2], mnew[2];
#pragma unroll
        for (int h = 0; h < 2; h++) {
            float other = *(float*)(sm8 + AO_RM + ((1 - wc2) * 64 + wr + rg + h * 8) * 4);
            mnew[h] = fmaxf(mrow[h], fmaxf(wmax[h], other));
            alpha[h] = __expf(mrow[h] - mnew[h]);
            mrow[h] = mnew[h];
        }
        float rsum[2] = {0.f, 0.f};
#pragma unroll
        for (int nt = 0; nt < 4; nt++) {
#pragma unroll
            for (int h = 0; h < 2; h++) {
                float p0 = __expf(s[nt][h * 2 + 0] - mnew[h]);
                float p1 = __expf(s[nt][h * 2 + 1] - mnew[h]);
                rsum[h] += p0 + p1;
                __nv_bfloat16 h0, l0, h1, l1;
                split_bf16(p0, h0, l0);
                split_bf16(p1, h1, l1);
                int ii = wr + rg + h * 8;
                int jj = wc2 * 32 + nt * 8 + c4 * 2;
                __nv_bfloat162 th; th.x = h0; th.y = h1;
                __nv_bfloat162 tl; tl.x = l0; tl.y = l1;
                *(__nv_bfloat162*)(sm8 + AO_PH + ii * AT_STRB + jj * 2) = th;
                *(__nv_bfloat162*)(sm8 + AO_PL + ii * AT_STRB + jj * 2) = tl;
            }
        }
#pragma unroll
        for (int h = 0; h < 2; h++) {
            rsum[h] += __shfl_xor_sync(0xffffffffu, rsum[h], 1);
            rsum[h] += __shfl_xor_sync(0xffffffffu, rsum[h], 2);
        }
        if (c4 == 0) {
            *(float*)(sm8 + AO_RS + (wc2 * 64 + wr + rg) * 4) = rsum[0];
            *(float*)(sm8 + AO_RS + (wc2 * 64 + wr + rg + 8) * 4) = rsum[1];
        }
        // rescale O
#pragma unroll
        for (int nt = 0; nt < 4; nt++) {
            o[nt][0] *= alpha[0]; o[nt][1] *= alpha[0];
            o[nt][2] *= alpha[1]; o[nt][3] *= alpha[1];
        }
        __syncthreads();
#pragma unroll
        for (int h = 0; h < 2; h++) {
            int row = wr + rg + h * 8;
            float tot = *(float*)(sm8 + AO_RS + row * 4) +
                        *(float*)(sm8 + AO_RS + (64 + row) * 4);
            lsum[h] = lsum[h] * alpha[h] + tot;
        }

        // ---- PV ----
#pragma unroll
        for (int ks = 0; ks < 4; ks++) {
            uint32_t pah[4], pal[4];
            uint32_t abase = su + (uint32_t)(wr * AT_STRB + ks * 32) + laneA;
            LDSM_X4(pah, abase + AO_PH);
            LDSM_X4(pal, abase + AO_PL);
            uint32_t vbh[2][4], vbl[2][4];
#pragma unroll
            for (int f = 0; f < 2; f++) {
                uint32_t baddr = su + (uint32_t)((ks * 16) * AT_STRB + (wc2 * 32 + f * 16) * 2) + laneBT;
                LDSM_X4_T(vbh[f], baddr + AO_VH);
                LDSM_X4_T(vbl[f], baddr + AO_VL);
            }
#pragma unroll
            for (int nt = 0; nt < 4; nt++) {
                int f = nt >> 1, sel = (nt & 1) * 2;
                mma_bf16(o[nt], pah, vbh[f][sel], vbh[f][sel + 1]);
                mma_bf16(o[nt], pah, vbl[f][sel], vbl[f][sel + 1]);
                mma_bf16(o[nt], pal, vbh[f][sel], vbh[f][sel + 1]);
            }
        }
    }

    // ---- epilogue: normalize, split, store attn planes ----
    float inv0 = 1.f / lsum[0], inv1 = 1.f / lsum[1];
#pragma unroll
    for (int nt = 0; nt < 4; nt++) {
        int d = wc2 * 32 + nt * 8 + c4 * 2;
        int r0g = I0 + wr + rg;
        size_t o0 = ((size_t)b * L_ + r0g) * 512 + n * 64 + d;
        size_t o1 = ((size_t)b * L_ + r0g + 8) * 512 + n * 64 + d;
        float v0 = o[nt][0] * inv0, v1 = o[nt][1] * inv0;
        float v2 = o[nt][2] * inv1, v3 = o[nt][3] * inv1;
        __nv_bfloat16 h0, l0, h1, l1;
        split_bf16(v0, h0, l0); split_bf16(v1, h1, l1);
        __nv_bfloat162 th; th.x = h0; th.y = h1;
        __nv_bfloat162 tl; tl.x = l0; tl.y = l1;
        *(__nv_bfloat162*)&g_attnh[o0] = th;
        *(__nv_bfloat162*)&g_attnl[o0] = tl;
        split_bf16(v2, h0, l0); split_bf16(v3, h1, l1);
        th.x = h0; th.y = h1; tl.x = l0; tl.y = l1;
        *(__nv_bfloat162*)&g_attnh[o1] = th;
        *(__nv_bfloat162*)&g_attnl[o1] = tl;
    }
}

// ================= layernorm (eps=1e-12) =================
template <bool SPLIT>
__global__ void ln_kernel(const float* __restrict__ in, const float* __restrict__ w,
                          const float* __restrict__ bparm, float* __restrict__ out,
                          __nv_bfloat16* __restrict__ oh, __nv_bfloat16* __restrict__ ol) {
    __shared__ float red[8];
    __shared__ float stat[2];
    int row = blockIdx.x, tid = threadIdx.x;
    const float* xr = in + (size_t)row * H_;
    float v0 = xr[tid], v1 = xr[tid + 256];
    float s = v0 + v1;
#pragma unroll
    for (int mk = 16; mk >= 1; mk >>= 1) s += __shfl_xor_sync(0xffffffffu, s, mk);
    if ((tid & 31) == 0) red[tid >> 5] = s;
    __syncthreads();
    if (tid == 0) {
        float t = 0;
#pragma unroll
        for (int i = 0; i < 8; i++) t += red[i];
        stat[0] = t * (1.0f / H_);
    }
    __syncthreads();
    float u = stat[0];
    float d0 = v0 - u, d1 = v1 - u;
    float q = d0 * d0 + d1 * d1;
#pragma unroll
    for (int mk = 16; mk >= 1; mk >>= 1) q += __shfl_xor_sync(0xffffffffu, q, mk);
    __syncthreads();
    if ((tid & 31) == 0) red[tid >> 5] = q;
    __syncthreads();
    if (tid == 0) {
        float t = 0;
#pragma unroll
        for (int i = 0; i < 8; i++) t += red[i];
        stat[1] = rsqrtf(t * (1.0f / H_) + 1e-12f);
    }
    __syncthreads();
    float inv = stat[1];
    float r0v = w[tid] * d0 * inv + bparm[tid];
    float r1v = w[tid + 256] * d1 * inv + bparm[tid + 256];
    out[(size_t)row * H_ + tid] = r0v;
    out[(size_t)row * H_ + tid + 256] = r1v;
    if (SPLIT) {
        __nv_bfloat16 h, l;
        split_bf16(r0v, h, l);
        oh[(size_t)row * H_ + tid] = h; ol[(size_t)row * H_ + tid] = l;
        split_bf16(r1v, h, l);
        oh[(size_t)row * H_ + tid + 256] = h; ol[(size_t)row * H_ + tid + 256] = l;
    }
}

// ================= launch =================
extern "C" void kernel_launch(void* const* d_in, const int* in_sizes, int n_in,
                              void* d_out, int out_size) {
    (void)in_sizes; (void)n_in; (void)out_size;
    const float* x  = (const float*)d_in[0];
    const float* pe = (const float*)d_in[1];
    const float* Wq = (const float*)d_in[2];
    const float* bq = (const float*)d_in[3];
    const float* Wk = (const float*)d_in[4];
    const float* bk = (const float*)d_in[5];
    const float* Wv = (const float*)d_in[6];
    const float* bv = (const float*)d_in[7];
    const float* Wr = (const float*)d_in[8];
    const float* br = (const float*)d_in[9];
    const float* cb = (const float*)d_in[10];
    const float* pb = (const float*)d_in[11];
    const float* Wc = (const float*)d_in[12];
    const float* bc = (const float*)d_in[13];
    const float* W1 = (const float*)d_in[14];
    const float* b1 = (const float*)d_in[15];
    const float* W2 = (const float*)d_in[16];
    const float* b2 = (const float*)d_in[17];
    const float* lnw = (const float*)d_in[18];
    const float* lnb = (const float*)d_in[19];
    float* out = (float*)d_out;

    __nv_bfloat16 *pxh, *pxl, *ppeh, *ppel, *pBqh, *pBql, *pBrh, *pBrl;
    __nv_bfloat16 *pWch, *pWcl, *pW1h, *pW1l, *pW2h, *pW2l;
    __nv_bfloat16 *path, *patl, *pah, *pal, *ph1h, *ph1l;
    float *pbqkv, *pbrp, *pr, *ppw, *py1, *pa, *py2;
    cudaGetSymbolAddress((void**)&pxh, g_xh);
    cudaGetSymbolAddress((void**)&pxl, g_xl);
    cudaGetSymbolAddress((void**)&ppeh, g_peh);
    cudaGetSymbolAddress((void**)&ppel, g_pel);
    cudaGetSymbolAddress((void**)&pBqh, g_Bqkvh);
    cudaGetSymbolAddress((void**)&pBql, g_Bqkvl);
    cudaGetSymbolAddress((void**)&pBrh, g_Brh);
    cudaGetSymbolAddress((void**)&pBrl, g_Brl);
    cudaGetSymbolAddress((void**)&pWch, g_Wch);
    cudaGetSymbolAddress((void**)&pWcl, g_Wcl);
    cudaGetSymbolAddress((void**)&pW1h, g_W1h);
    cudaGetSymbolAddress((void**)&pW1l, g_W1l);
    cudaGetSymbolAddress((void**)&pW2h, g_W2h);
    cudaGetSymbolAddress((void**)&pW2l, g_W2l);
    cudaGetSymbolAddress((void**)&path, g_attnh);
    cudaGetSymbolAddress((void**)&patl, g_attnl);
    cudaGetSymbolAddress((void**)&pah, g_ah);
    cudaGetSymbolAddress((void**)&pal, g_al);
    cudaGetSymbolAddress((void**)&ph1h, g_h1h);
    cudaGetSymbolAddress((void**)&ph1l, g_h1l);
    cudaGetSymbolAddress((void**)&pbqkv, g_bqkv);
    cudaGetSymbolAddress((void**)&pbrp, g_brp);
    cudaGetSymbolAddress((void**)&pr, g_rb);
    cudaGetSymbolAddress((void**)&ppw, g_pw);
    cudaGetSymbolAddress((void**)&py1, g_y1);
    cudaGetSymbolAddress((void**)&pa, g_a);
    cudaGetSymbolAddress((void**)&py2, g_y2);

    cudaFuncSetAttribute(attn_mma, cudaFuncAttributeMaxDynamicSharedMemorySize, ATTN_SMEM2);
    cudaFuncSetAttribute(gemm_hmma<0>, cudaFuncAttributeMaxDynamicSharedMemorySize, HMMA_SMEM);
    cudaFuncSetAttribute(gemm_hmma<1>, cudaFuncAttributeMaxDynamicSharedMemorySize, HMMA_SMEM);
    cudaFuncSetAttribute(gemm_hmma<2>, cudaFuncAttributeMaxDynamicSharedMemorySize, HMMA_SMEM);
    cudaFuncSetAttribute(gemm_hmma<3>, cudaFuncAttributeMaxDynamicSharedMemorySize, HMMA_SMEM);

    // converts + packs
    conv_split<<<2048, 256>>>(x, pxh, pxl, B_ * L_ * H_);
    conv_split<<<1024, 256>>>(pe, ppeh, ppel, L_ * H_);
    conv_split<<<512, 256>>>(Wc, pWch, pWcl, H_ * H_);
    conv_split<<<512, 256>>>(W1, pW1h, pW1l, H_ * H_);
    conv_split<<<512, 256>>>(W2, pW2h, pW2l, H_ * H_);
    pack_qkvr<<<768, 256>>>(Wq, bq, Wk, bk, Wv, bv, Wr, br);

    // QKV: scatter into split qc/k/v planes (content_bias folded via res=cb)
    gemm_hmma<0><<<dim3(24, 64), 256, HMMA_SMEM>>>(
        pxh, pxl, pBqh, pBql, pbqkv, cb, nullptr, nullptr, nullptr, 1536);

    // R: scatter into float r + split planes
    gemm_hmma<1><<<dim3(8, 16), 256, HMMA_SMEM>>>(
        ppeh, ppel, pBrh, pBrl, pbrp, nullptr, pr, nullptr, nullptr, 512);

    pw_kernel<<<dim3(16, 8), 128>>>(cb, pb, ppw);

    // tensor-core attention
    attn_mma<<<dim3(32, 32), 256, ATTN_SMEM2>>>();

    // Wc + residual(x) -> y1
    gemm_hmma<2><<<dim3(8, 64), 256, HMMA_SMEM>>>(
        path, patl, pWch, pWcl, bc, x, py1, nullptr, nullptr, 512);

    ln_kernel<true><<<B_ * L_, 256>>>(py1, lnw, lnb, pa, pah, pal);

    // FFN up + GELU -> h1 planes
    gemm_hmma<3><<<dim3(8, 64), 256, HMMA_SMEM>>>(
        pah, pal, pW1h, pW1l, b1, nullptr, nullptr, ph1h, ph1l, 512);

    // FFN down + residual(a) -> y2
    gemm_hmma<2><<<dim3(8, 64), 256, HMMA_SMEM>>>(
        ph1h, ph1l, pW2h, pW2l, b2, pa, py2, nullptr, nullptr, 512);

    ln_kernel<false><<<B_ * L_, 256>>>(py2, lnw, lnb, out, nullptr, nullptr);
}

// round 12
// speedup vs baseline: 2.8310x; 1.3924x over previous
#include <cuda_runtime.h>
#include <cuda_bf16.h>
#include <cuda_fp16.h>
#include <math.h>
#include <stdint.h>

#define B_ 4
#define L_ 2048
#define H_ 512
#define N_ 8
#define D_ 64

typedef unsigned long long ull;

// ================= common helpers =================
__device__ __forceinline__ uint32_t smem_to_u32(const void* p) {
    uint32_t a;
    asm("{ .reg .u64 t; cvta.to.shared.u64 t, %1; cvt.u32.u64 %0, t; }" : "=r"(a) : "l"(p));
    return a;
}

#define LDSM_X4(r, addr)                                                          \
    asm volatile("ldmatrix.sync.aligned.m8n8.x4.shared.b16 {%0,%1,%2,%3}, [%4];"  \
        : "=r"((r)[0]), "=r"((r)[1]), "=r"((r)[2]), "=r"((r)[3]) : "r"(addr))

#define LDSM_X4_T(r, addr)                                                              \
    asm volatile("ldmatrix.sync.aligned.m8n8.x4.trans.shared.b16 {%0,%1,%2,%3}, [%4];"  \
        : "=r"((r)[0]), "=r"((r)[1]), "=r"((r)[2]), "=r"((r)[3]) : "r"(addr))

__device__ __forceinline__ void mma_bf16(float* c, const uint32_t* a, uint32_t b0, uint32_t b1) {
    asm volatile(
        "mma.sync.aligned.m16n8k16.row.col.f32.bf16.bf16.f32 "
        "{%0,%1,%2,%3}, {%4,%5,%6,%7}, {%8,%9}, {%0,%1,%2,%3};"
        : "+f"(c[0]), "+f"(c[1]), "+f"(c[2]), "+f"(c[3])
        : "r"(a[0]), "r"(a[1]), "r"(a[2]), "r"(a[3]), "r"(b0), "r"(b1));
}

__device__ __forceinline__ void mma_f16(float* c, const uint32_t* a, uint32_t b0, uint32_t b1) {
    asm volatile(
        "mma.sync.aligned.m16n8k16.row.col.f32.f16.f16.f32 "
        "{%0,%1,%2,%3}, {%4,%5,%6,%7}, {%8,%9}, {%0,%1,%2,%3};"
        : "+f"(c[0]), "+f"(c[1]), "+f"(c[2]), "+f"(c[3])
        : "r"(a[0]), "r"(a[1]), "r"(a[2]), "r"(a[3]), "r"(b0), "r"(b1));
}

#define CP_ASYNC16(dst, src) asm volatile("cp.async.cg.shared.global [%0], [%1], 16;" :: "r"(dst), "l"(src))
#define CP_COMMIT()          asm volatile("cp.async.commit_group;" ::: "memory")
#define CP_WAIT(n)           asm volatile("cp.async.wait_group %0;" :: "n"(n) : "memory")

// ================= scratch =================
__device__ __nv_bfloat16 g_xh[B_ * L_ * H_];
__device__ __nv_bfloat16 g_xl[B_ * L_ * H_];
__device__ __nv_bfloat16 g_peh[L_ * H_];
__device__ __nv_bfloat16 g_pel[L_ * H_];
__device__ __nv_bfloat16 g_Bqkvh[3 * H_ * H_];
__device__ __nv_bfloat16 g_Bqkvl[3 * H_ * H_];
__device__ __nv_bfloat16 g_Brh[H_ * H_];
__device__ __nv_bfloat16 g_Brl[H_ * H_];
__device__ __nv_bfloat16 g_Wch[H_ * H_];
__device__ __nv_bfloat16 g_Wcl[H_ * H_];
__device__ __nv_bfloat16 g_W1h[H_ * H_];
__device__ __nv_bfloat16 g_W1l[H_ * H_];
__device__ __nv_bfloat16 g_W2h[H_ * H_];
__device__ __nv_bfloat16 g_W2l[H_ * H_];
__device__ float g_bqkv[3 * H_];
__device__ float g_brp[H_];
// attention operands: single fp16 plane each
__device__ __half g_qf[32 * L_ * D_];
__device__ __half g_kf[32 * L_ * D_];
__device__ __half g_vf[32 * L_ * D_];
__device__ __half g_rf[N_ * L_ * D_];
__device__ float g_rb[N_ * L_ * D_];
__device__ float g_pw[N_ * L_];
__device__ __nv_bfloat16 g_attnh[B_ * L_ * H_];
__device__ __nv_bfloat16 g_attnl[B_ * L_ * H_];
__device__ float g_y1[B_ * L_ * H_];
__device__ float g_a[B_ * L_ * H_];
__device__ __nv_bfloat16 g_ah[B_ * L_ * H_];
__device__ __nv_bfloat16 g_al[B_ * L_ * H_];
__device__ __nv_bfloat16 g_h1h[B_ * L_ * H_];
__device__ __nv_bfloat16 g_h1l[B_ * L_ * H_];
__device__ float g_y2[B_ * L_ * H_];

// ================= split-convert =================
__device__ __forceinline__ void split_bf16(float v, __nv_bfloat16& h, __nv_bfloat16& l) {
    h = __float2bfloat16(v);
    l = __float2bfloat16(v - __bfloat162float(h));
}

__global__ void conv_split(const float* __restrict__ src, __nv_bfloat16* __restrict__ dh,
                           __nv_bfloat16* __restrict__ dl, int n) {
    int i = blockIdx.x * 256 + threadIdx.x;
    int stride = gridDim.x * 256;
    for (; i < n; i += stride) {
        __nv_bfloat16 h, l;
        split_bf16(src[i], h, l);
        dh[i] = h; dl[i] = l;
    }
}

__global__ void pack_qkvr(const float* __restrict__ Wq, const float* __restrict__ bq,
                          const float* __restrict__ Wk, const float* __restrict__ bk,
                          const float* __restrict__ Wv, const float* __restrict__ bv,
                          const float* __restrict__ Wr, const float* __restrict__ br) {
    int idx = blockIdx.x * 256 + threadIdx.x;
    int stride = gridDim.x * 256;
    for (int i = idx; i < 1536 * 512; i += stride) {
        int c = i >> 9, h = i & 511;
        int mat = c >> 9, rem = c & 511, n = rem >> 6, d = rem & 63;
        const float* W = (mat == 0) ? Wq : ((mat == 1) ? Wk : Wv);
        __nv_bfloat16 hh, ll;
        split_bf16(W[(n * 512 + h) * 64 + d], hh, ll);
        g_Bqkvh[i] = hh; g_Bqkvl[i] = ll;
    }
    for (int i = idx; i < 512 * 512; i += stride) {
        int c = i >> 9, h = i & 511;
        int n = c >> 6, d = c & 63;
        __nv_bfloat16 hh, ll;
        split_bf16(Wr[(n * 512 + h) * 64 + d], hh, ll);
        g_Brh[i] = hh; g_Brl[i] = ll;
    }
    for (int i = idx; i < 1536; i += stride) {
        int mat = i >> 9, rem = i & 511;
        const float* bb = (mat == 0) ? bq : ((mat == 1) ? bk : bv);
        g_bqkv[i] = bb[rem];
    }
    for (int i = idx; i < 512; i += stride) g_brp[i] = br[i];
}

__global__ void pw_kernel(const float* __restrict__ cb, const float* __restrict__ pb,
                          float* __restrict__ pwg) {
    int n = blockIdx.y;
    int p = blockIdx.x * 128 + threadIdx.x;
    const float* rp = &g_rb[(n * 2048 + p) * 64];
    float s = 0.f;
#pragma unroll 16
    for (int d = 0; d < 64; d++) s += (pb[n * 64 + d] - cb[n * 64 + d]) * rp[d];
    pwg[n * 2048 + p] = s;
}

__device__ __forceinline__ float gelu_f(float v) {
    return 0.5f * v * (1.0f + erff(v * 0.70710678118654752f));
}

// ================= HMMA GEMM: 128x64 block, 8 warps 32x32, K=512, 3-pass bf16 split =================
// MODE 0: qkv scatter -> fp16 planes (+cb on q via res)   MODE 1: r scatter -> float + fp16 plane
// MODE 2: Cf = acc + bias + res                           MODE 3: gelu(acc+bias) -> Ch/Cl
#define GSTRIDE 80
#define OFF_AH 0
#define OFF_AL 10240
#define OFF_BH 20480
#define OFF_BL 25600
#define BUF_SZ 30720
#define HMMA_SMEM (2 * BUF_SZ + 128)

template <int MODE>
__global__ void __launch_bounds__(256, 2)
gemm_hmma(const __nv_bfloat16* __restrict__ Ah, const __nv_bfloat16* __restrict__ Al,
          const __nv_bfloat16* __restrict__ Bh, const __nv_bfloat16* __restrict__ Bl,
          const float* __restrict__ bias, const float* __restrict__ res,
          float* __restrict__ Cf, __nv_bfloat16* __restrict__ Ch, __nv_bfloat16* __restrict__ Cl,
          int Nc) {
    extern __shared__ char smem[];
    const uint32_t su = smem_to_u32(smem);
    const int tid = threadIdx.x;
    const int wid = tid >> 5, lane = tid & 31;
    const int m0 = blockIdx.y * 128, n0 = blockIdx.x * 64;

    const int wm = (wid & 3) * 32;
    const int wn = (wid >> 2) * 32;

    const uint32_t laneA = (uint32_t)((((lane >> 3) & 1) * 8 + (lane & 7)) * GSTRIDE + (lane >> 4) * 16);
    const uint32_t laneB = (uint32_t)((((lane >> 4) & 1) * 8 + (lane & 7)) * GSTRIDE + ((lane >> 3) & 1) * 16);

    const int arow = tid >> 1;
    const int acp0 = (tid & 1) * 2;
    const int brow = tid >> 2;
    const int bcp = tid & 3;

    float c[2][4][4];
#pragma unroll
    for (int mi = 0; mi < 2; mi++)
#pragma unroll
        for (int nt = 0; nt < 4; nt++)
#pragma unroll
            for (int e = 0; e < 4; e++) c[mi][nt][e] = 0.f;

    auto issue_stage = [&](int s) {
        const int k0 = s * 32;
        const uint32_t bufo = su + (uint32_t)((s & 1) * BUF_SZ);
        const __nv_bfloat16* gAh = Ah + (size_t)(m0 + arow) * 512 + k0 + acp0 * 8;
        const __nv_bfloat16* gAl = Al + (size_t)(m0 + arow) * 512 + k0 + acp0 * 8;
        uint32_t dA = bufo + (uint32_t)(arow * GSTRIDE + acp0 * 16);
        CP_ASYNC16(dA + OFF_AH, gAh);
        CP_ASYNC16(dA + OFF_AH + 16, gAh + 8);
        CP_ASYNC16(dA + OFF_AL, gAl);
        CP_ASYNC16(dA + OFF_AL + 16, gAl + 8);
        {
            const __nv_bfloat16* gBh = Bh + (size_t)(n0 + brow) * 512 + k0 + bcp * 8;
            const __nv_bfloat16* gBl = Bl + (size_t)(n0 + brow) * 512 + k0 + bcp * 8;
            uint32_t dB = bufo + (uint32_t)(brow * GSTRIDE + bcp * 16);
            CP_ASYNC16(dB + OFF_BH, gBh);
            CP_ASYNC16(dB + OFF_BL, gBl);
        }
    };

    issue_stage(0);
    CP_COMMIT();

    for (int s = 0; s < 16; s++) {
        if (s + 1 < 16) {
            issue_stage(s + 1);
            CP_COMMIT();
            CP_WAIT(1);
        } else {
            CP_WAIT(0);
        }
        __syncthreads();
        const uint32_t bufo = su + (uint32_t)((s & 1) * BUF_SZ);
#pragma unroll
        for (int ks = 0; ks < 2; ks++) {
            uint32_t ah[2][4], al[2][4], bh[2][4], bl[2][4];
#pragma unroll
            for (int mi = 0; mi < 2; mi++) {
                uint32_t aaddr = bufo + (uint32_t)((wm + mi * 16) * GSTRIDE + ks * 32) + laneA;
                LDSM_X4(ah[mi], aaddr + OFF_AH);
                LDSM_X4(al[mi], aaddr + OFF_AL);
            }
#pragma unroll
            for (int ni = 0; ni < 2; ni++) {
                uint32_t baddr = bufo + (uint32_t)((wn + ni * 16) * GSTRIDE + ks * 32) + laneB;
                LDSM_X4(bh[ni], baddr + OFF_BH);
                LDSM_X4(bl[ni], baddr + OFF_BL);
            }
#pragma unroll
            for (int mi = 0; mi < 2; mi++)
#pragma unroll
                for (int nt = 0; nt < 4; nt++) {
                    int ni = nt >> 1, sel = (nt & 1) * 2;
                    mma_bf16(c[mi][nt], ah[mi], bh[ni][sel], bh[ni][sel + 1]);
                    mma_bf16(c[mi][nt], ah[mi], bl[ni][sel], bl[ni][sel + 1]);
                    mma_bf16(c[mi][nt], al[mi], bh[ni][sel], bh[ni][sel + 1]);
                }
        }
        __syncthreads();
    }

    // -------- epilogue --------
#pragma unroll
    for (int mi = 0; mi < 2; mi++)
#pragma unroll
        for (int nt = 0; nt < 4; nt++) {
#pragma unroll
            for (int hh = 0; hh < 2; hh++) {
                int m = m0 + wm + mi * 16 + (lane >> 2) + hh * 8;
                int cg = n0 + wn + nt * 8 + (lane & 3) * 2;
                float v0 = c[mi][nt][hh * 2 + 0] + __ldg(&bias[cg]);
                float v1 = c[mi][nt][hh * 2 + 1] + __ldg(&bias[cg + 1]);
                if (MODE == 0) {
                    int mat = cg >> 9, rem = cg & 511, n2 = rem >> 6, d = rem & 63;
                    int bI = m >> 11, l = m & 2047;
                    size_t o = ((size_t)(bI * 8 + n2) * 2048 + l) * 64 + d;
                    if (mat == 0) { v0 += __ldg(&res[rem]); v1 += __ldg(&res[rem + 1]); }
                    __half2 t2;
                    t2.x = __float2half(v0); t2.y = __float2half(v1);
                    if (mat == 0)      *(__half2*)&g_qf[o] = t2;
                    else if (mat == 1) *(__half2*)&g_kf[o] = t2;
                    else               *(__half2*)&g_vf[o] = t2;
                } else if (MODE == 1) {
                    int n2 = cg >> 6, d = cg & 63;
                    size_t o = ((size_t)n2 * 2048 + m) * 64 + d;
                    Cf[o] = v0; Cf[o + 1] = v1;
                    __half2 t2;
                    t2.x = __float2half(v0); t2.y = __float2half(v1);
                    *(__half2*)&g_rf[o] = t2;
                } else if (MODE == 2) {
                    size_t o = (size_t)m * Nc + cg;
                    Cf[o] = v0 + res[o];
                    Cf[o + 1] = v1 + res[o + 1];
                } else {
                    float g0 = gelu_f(v0), g1 = gelu_f(v1);
                    __nv_bfloat16 h0, l0, h1, l1;
                    split_bf16(g0, h0, l0); split_bf16(g1, h1, l1);
                    size_t o = (size_t)m * 512 + cg;
                    Ch[o] = h0; Ch[o + 1] = h1;
                    Cl[o] = l0; Cl[o + 1] = l1;
                }
            }
        }
}

// ================= tensor-core flash attention (single-pass fp16) =================
// s[ii][jj] = (qc·k + T[ii][63-ii+jj]) / 8, T = qc·r_window + pw
// 64 q-rows per CTA, 64-key j-tiles, 8 warps: (wid&3)->16-row group, (wid>>2)->col half.
#define AT_STRB 144                      // 72 halves per row
#define AO_Q  0
#define AO_K  9216
#define AO_V  18432
#define AO_R  27648
#define AO_P  46080
#define AO_TS 55296
#define AO_PW 90112
#define AO_RM 90624
#define AO_RS 91136
#define ATTN_SMEM2 91648

__global__ void __launch_bounds__(256, 2)
attn_mma() {
    extern __shared__ char sm8[];
    const uint32_t su = smem_to_u32(sm8);
    const int tid = threadIdx.x, wid = tid >> 5, lane = tid & 31;
    const int ib = blockIdx.x, bn = blockIdx.y;
    const int n = bn & 7, b = bn >> 3;
    const int I0 = ib * 64;
    const int wr = (wid & 3) * 16, wc2 = wid >> 2;
    const int rg = lane >> 2, c4 = lane & 3;

    const uint32_t laneA  = (uint32_t)((((lane >> 3) & 1) * 8 + (lane & 7)) * AT_STRB + (lane >> 4) * 16);
    const uint32_t laneB  = (uint32_t)((((lane >> 4) & 1) * 8 + (lane & 7)) * AT_STRB + ((lane >> 3) & 1) * 16);
    const uint32_t laneBT = (uint32_t)((lane & 15) * AT_STRB + (lane >> 4) * 16);

    // load Q once: 64x64 fp16
    {
        const int row = tid >> 2, cb8 = (tid & 3) * 16;
        size_t g = ((size_t)bn * L_ + I0 + row) * 64 + cb8;
        const uint4* s1 = (const uint4*)&g_qf[g];
        uint32_t d0 = (uint32_t)(row * AT_STRB + cb8 * 2);
        *(uint4*)(sm8 + AO_Q + d0) = s1[0];
        *(uint4*)(sm8 + AO_Q + d0 + 16) = s1[1];
    }

    float mrow[2] = {-1e30f, -1e30f};
    float lsum[2] = {0.f, 0.f};
    float o[4][4];
#pragma unroll
    for (int nt = 0; nt < 4; nt++)
#pragma unroll
        for (int e = 0; e < 4; e++) o[nt][e] = 0.f;

    for (int jb = 0; jb <= ib; jb++) {
        const int J0 = jb * 64;
        const int pmin = L_ - 64 - I0 + J0;
        __syncthreads();   // prev-iteration PV reads done
        // ---- loads: K,V (64x64), R (128x64), pw (128) ----
        {
            const int row = tid >> 2, cb8 = (tid & 3) * 16;
            uint32_t d0 = (uint32_t)(row * AT_STRB + cb8 * 2);
            size_t gk = ((size_t)bn * L_ + J0 + row) * 64 + cb8;
            const uint4* s1 = (const uint4*)&g_kf[gk];
            const uint4* s3 = (const uint4*)&g_vf[gk];
            *(uint4*)(sm8 + AO_K + d0) = s1[0]; *(uint4*)(sm8 + AO_K + d0 + 16) = s1[1];
            *(uint4*)(sm8 + AO_V + d0) = s3[0]; *(uint4*)(sm8 + AO_V + d0 + 16) = s3[1];
#pragma unroll
            for (int t = 0; t < 2; t++) {
                int pp = row + t * 64;
                int p = pmin + pp;
                uint32_t dr = (uint32_t)(pp * AT_STRB + cb8 * 2);
                uint4 r0 = make_uint4(0, 0, 0, 0), r1 = r0;
                if (p < L_) {
                    size_t gr = ((size_t)n * L_ + p) * 64 + cb8;
                    const uint4* t1 = (const uint4*)&g_rf[gr];
                    r0 = t1[0]; r1 = t1[1];
                }
                *(uint4*)(sm8 + AO_R + dr) = r0; *(uint4*)(sm8 + AO_R + dr + 16) = r1;
            }
            if (tid < 128) {
                int p = pmin + tid;
                *(float*)(sm8 + AO_PW + tid * 4) = (p < L_) ? g_pw[n * 2048 + p] : 0.f;
            }
        }
        __syncthreads();

        // ---- QK (regs) + T (-> Ts smem) ----
        float sQK[4][4], tacc[8][4];
#pragma unroll
        for (int nt = 0; nt < 4; nt++)
#pragma unroll
            for (int e = 0; e < 4; e++) sQK[nt][e] = 0.f;
#pragma unroll
        for (int nt = 0; nt < 8; nt++)
#pragma unroll
            for (int e = 0; e < 4; e++) tacc[nt][e] = 0.f;

#pragma unroll
        for (int ks = 0; ks < 4; ks++) {
            uint32_t aq[4];
            uint32_t abase = su + (uint32_t)(wr * AT_STRB + ks * 32) + laneA;
            LDSM_X4(aq, abase + AO_Q);
            uint32_t kb[2][4];
#pragma unroll
            for (int f = 0; f < 2; f++) {
                uint32_t baddr = su + (uint32_t)((wc2 * 32 + f * 16) * AT_STRB + ks * 32) + laneB;
                LDSM_X4(kb[f], baddr + AO_K);
            }
#pragma unroll
            for (int nt = 0; nt < 4; nt++) {
                int f = nt >> 1, sel = (nt & 1) * 2;
                mma_f16(sQK[nt], aq, kb[f][sel], kb[f][sel + 1]);
            }
            uint32_t rb[4][4];
#pragma unroll
            for (int f = 0; f < 4; f++) {
                uint32_t baddr = su + (uint32_t)((wc2 * 64 + f * 16) * AT_STRB + ks * 32) + laneB;
                LDSM_X4(rb[f], baddr + AO_R);
            }
#pragma unroll
            for (int nt = 0; nt < 8; nt++) {
                int f = nt >> 1, sel = (nt & 1) * 2;
                mma_f16(tacc[nt], aq, rb[f][sel], rb[f][sel + 1]);
            }
        }
        // store T (+pw) to smem
#pragma unroll
        for (int nt = 0; nt < 8; nt++) {
#pragma unroll
            for (int e = 0; e < 4; e++) {
                int row = wr + rg + (e >> 1) * 8;
                int col = wc2 * 64 + nt * 8 + c4 * 2 + (e & 1);
                *(float*)(sm8 + AO_TS + (row * 136 + col) * 4) =
                    tacc[nt][e] + *(float*)(sm8 + AO_PW + col * 4);
            }
        }
        __syncthreads();

        // ---- softmax ----
        const bool diag = (jb == ib);
        float s[4][4];
        float wmax[2] = {-1e30f, -1e30f};
#pragma unroll
        for (int nt = 0; nt < 4; nt++) {
#pragma unroll
            for (int e = 0; e < 4; e++) {
                int ii = wr + rg + (e >> 1) * 8;
                int jj = wc2 * 32 + nt * 8 + c4 * 2 + (e & 1);
                float v = sQK[nt][e] + *(float*)(sm8 + AO_TS + (ii * 136 + (63 - ii + jj)) * 4);
                v *= 0.125f;
                if (diag && jj > ii) v = -1e30f;
                s[nt][e] = v;
                wmax[e >> 1] = fmaxf(wmax[e >> 1], v);
            }
        }
#pragma unroll
        for (int h = 0; h < 2; h++) {
            wmax[h] = fmaxf(wmax[h], __shfl_xor_sync(0xffffffffu, wmax[h], 1));
            wmax[h] = fmaxf(wmax[h], __shfl_xor_sync(0xffffffffu, wmax[h], 2));
        }
        if (c4 == 0) {
            *(float*)(sm8 + AO_RM + (wc2 * 64 + wr + rg) * 4) = wmax[0];
            *(float*)(sm8 + AO_RM + (wc2 * 64 + wr + rg + 8) * 4) = wmax[1];
        }
        __syncthreads();
        float alpha[2], mnew[2];
#pragma unroll
        for (int h = 0; h < 2; h++) {
            float other = *(float*)(sm8 + AO_RM + ((1 - wc2) * 64 + wr + rg + h * 8) * 4);
            mnew[h] = fmaxf(mrow[h], fmaxf(wmax[h], other));
            alpha[h] = __expf(mrow[h] - mnew[h]);
            mrow[h] = mnew[h];
        }
        float rsum[2] = {0.f, 0.f};
#pragma unroll
        for (int nt = 0; nt < 4; nt++) {
#pragma unroll
            for (int h = 0; h < 2; h++) {
                float p0 = __expf(s[nt][h * 2 + 0] - mnew[h]);
                float p1 = __expf(s[nt][h * 2 + 1] - mnew[h]);
                rsum[h] += p0 + p1;
                int ii = wr + rg + h * 8;
                int jj = wc2 * 32 + nt * 8 + c4 * 2;
                __half2 t2;
                t2.x = __float2half(p0); t2.y = __float2half(p1);
                *(__half2*)(sm8 + AO_P + ii * AT_STRB + jj * 2) = t2;
            }
        }
#pragma unroll
        for (int h = 0; h < 2; h++) {
            rsum[h] += __shfl_xor_sync(0xffffffffu, rsum[h], 1);
            rsum[h] += __shfl_xor_sync(0xffffffffu, rsum[h], 2);
        }
        if (c4 == 0) {
            *(float*)(sm8 + AO_RS + (wc2 * 64 + wr + rg) * 4) = rsum[0];
            *(float*)(sm8 + AO_RS + (wc2 * 64 + wr + rg + 8) * 4) = rsum[1];
        }
        // rescale O
#pragma unroll
        for (int nt = 0; nt < 4; nt++) {
            o[nt][0] *= alpha[0]; o[nt][1] *= alpha[0];
            o[nt][2] *= alpha[1]; o[nt][3] *= alpha[1];
        }
        __syncthreads();
#pragma unroll
        for (int h = 0; h < 2; h++) {
            int row = wr + rg + h * 8;
            float tot = *(float*)(sm8 + AO_RS + row * 4) +
                        *(float*)(sm8 + AO_RS + (64 + row) * 4);
            lsum[h] = lsum[h] * alpha[h] + tot;
        }

        // ---- PV ----
#pragma unroll
        for (int ks = 0; ks < 4; ks++) {
            uint32_t pa[4];
            uint32_t abase = su + (uint32_t)(wr * AT_STRB + ks * 32) + laneA;
            LDSM_X4(pa, abase + AO_P);
            uint32_t vb[2][4];
#pragma unroll
            for (int f = 0; f < 2; f++) {
                uint32_t baddr = su + (uint32_t)((ks * 16) * AT_STRB + (wc2 * 32 + f * 16) * 2) + laneBT;
                LDSM_X4_T(vb[f], baddr + AO_V);
            }
#pragma unroll
            for (int nt = 0; nt < 4; nt++) {
                int f = nt >> 1, sel = (nt & 1) * 2;
                mma_f16(o[nt], pa, vb[f][sel], vb[f][sel + 1]);
            }
        }
    }

    // ---- epilogue: normalize, split, store attn planes ----
    float inv0 = 1.f / lsum[0], inv1 = 1.f / lsum[1];
#pragma unroll
    for (int nt = 0; nt < 4; nt++) {
        int d = wc2 * 32 + nt * 8 + c4 * 2;
        int r0g = I0 + wr + rg;
        size_t o0 = ((size_t)b * L_ + r0g) * 512 + n * 64 + d;
        size_t o1 = ((size_t)b * L_ + r0g + 8) * 512 + n * 64 + d;
        float v0 = o[nt][0] * inv0, v1 = o[nt][1] * inv0;
        float v2 = o[nt][2] * inv1, v3 = o[nt][3] * inv1;
        __nv_bfloat16 h0, l0, h1, l1;
        split_bf16(v0, h0, l0); split_bf16(v1, h1, l1);
        __nv_bfloat162 th; th.x = h0; th.y = h1;
        __nv_bfloat162 tl; tl.x = l0; tl.y = l1;
        *(__nv_bfloat162*)&g_attnh[o0] = th;
        *(__nv_bfloat162*)&g_attnl[o0] = tl;
        split_bf16(v2, h0, l0); split_bf16(v3, h1, l1);
        th.x = h0; th.y = h1; tl.x = l0; tl.y = l1;
        *(__nv_bfloat162*)&g_attnh[o1] = th;
        *(__nv_bfloat162*)&g_attnl[o1] = tl;
    }
}

// ================= layernorm (eps=1e-12) =================
template <bool SPLIT>
__global__ void ln_kernel(const float* __restrict__ in, const float* __restrict__ w,
                          const float* __restrict__ bparm, float* __restrict__ out,
                          __nv_bfloat16* __restrict__ oh, __nv_bfloat16* __restrict__ ol) {
    __shared__ float red[8];
    __shared__ float stat[2];
    int row = blockIdx.x, tid = threadIdx.x;
    const float* xr = in + (size_t)row * H_;
    float v0 = xr[tid], v1 = xr[tid + 256];
    float s = v0 + v1;
#pragma unroll
    for (int mk = 16; mk >= 1; mk >>= 1) s += __shfl_xor_sync(0xffffffffu, s, mk);
    if ((tid & 31) == 0) red[tid >> 5] = s;
    __syncthreads();
    if (tid == 0) {
        float t = 0;
#pragma unroll
        for (int i = 0; i < 8; i++) t += red[i];
        stat[0] = t * (1.0f / H_);
    }
    __syncthreads();
    float u = stat[0];
    float d0 = v0 - u, d1 = v1 - u;
    float q = d0 * d0 + d1 * d1;
#pragma unroll
    for (int mk = 16; mk >= 1; mk >>= 1) q += __shfl_xor_sync(0xffffffffu, q, mk);
    __syncthreads();
    if ((tid & 31) == 0) red[tid >> 5] = q;
    __syncthreads();
    if (tid == 0) {
        float t = 0;
#pragma unroll
        for (int i = 0; i < 8; i++) t += red[i];
        stat[1] = rsqrtf(t * (1.0f / H_) + 1e-12f);
    }
    __syncthreads();
    float inv = stat[1];
    float r0v = w[tid] * d0 * inv + bparm[tid];
    float r1v = w[tid + 256] * d1 * inv + bparm[tid + 256];
    out[(size_t)row * H_ + tid] = r0v;
    out[(size_t)row * H_ + tid + 256] = r1v;
    if (SPLIT) {
        __nv_bfloat16 h, l;
        split_bf16(r0v, h, l);
        oh[(size_t)row * H_ + tid] = h; ol[(size_t)row * H_ + tid] = l;
        split_bf16(r1v, h, l);
        oh[(size_t)row * H_ + tid + 256] = h; ol[(size_t)row * H_ + tid + 256] = l;
    }
}

// ================= launch =================
extern "C" void kernel_launch(void* const* d_in, const int* in_sizes, int n_in,
                              void* d_out, int out_size) {
    (void)in_sizes; (void)n_in; (void)out_size;
    const float* x  = (const float*)d_in[0];
    const float* pe = (const float*)d_in[1];
    const float* Wq = (const float*)d_in[2];
    const float* bq = (const float*)d_in[3];
    const float* Wk = (const float*)d_in[4];
    const float* bk = (const float*)d_in[5];
    const float* Wv = (const float*)d_in[6];
    const float* bv = (const float*)d_in[7];
    const float* Wr = (const float*)d_in[8];
    const float* br = (const float*)d_in[9];
    const float* cb = (const float*)d_in[10];
    const float* pb = (const float*)d_in[11];
    const float* Wc = (const float*)d_in[12];
    const float* bc = (const float*)d_in[13];
    const float* W1 = (const float*)d_in[14];
    const float* b1 = (const float*)d_in[15];
    const float* W2 = (const float*)d_in[16];
    const float* b2 = (const float*)d_in[17];
    const float* lnw = (const float*)d_in[18];
    const float* lnb = (const float*)d_in[19];
    float* out = (float*)d_out;

    __nv_bfloat16 *pxh, *pxl, *ppeh, *ppel, *pBqh, *pBql, *pBrh, *pBrl;
    __nv_bfloat16 *pWch, *pWcl, *pW1h, *pW1l, *pW2h, *pW2l;
    __nv_bfloat16 *path, *patl, *pah, *pal, *ph1h, *ph1l;
    float *pbqkv, *pbrp, *pr, *ppw, *py1, *pa, *py2;
    cudaGetSymbolAddress((void**)&pxh, g_xh);
    cudaGetSymbolAddress((void**)&pxl, g_xl);
    cudaGetSymbolAddress((void**)&ppeh, g_peh);
    cudaGetSymbolAddress((void**)&ppel, g_pel);
    cudaGetSymbolAddress((void**)&pBqh, g_Bqkvh);
    cudaGetSymbolAddress((void**)&pBql, g_Bqkvl);
    cudaGetSymbolAddress((void**)&pBrh, g_Brh);
    cudaGetSymbolAddress((void**)&pBrl, g_Brl);
    cudaGetSymbolAddress((void**)&pWch, g_Wch);
    cudaGetSymbolAddress((void**)&pWcl, g_Wcl);
    cudaGetSymbolAddress((void**)&pW1h, g_W1h);
    cudaGetSymbolAddress((void**)&pW1l, g_W1l);
    cudaGetSymbolAddress((void**)&pW2h, g_W2h);
    cudaGetSymbolAddress((void**)&pW2l, g_W2l);
    cudaGetSymbolAddress((void**)&path, g_attnh);
    cudaGetSymbolAddress((void**)&patl, g_attnl);
    cudaGetSymbolAddress((void**)&pah, g_ah);
    cudaGetSymbolAddress((void**)&pal, g_al);
    cudaGetSymbolAddress((void**)&ph1h, g_h1h);
    cudaGetSymbolAddress((void**)&ph1l, g_h1l);
    cudaGetSymbolAddress((void**)&pbqkv, g_bqkv);
    cudaGetSymbolAddress((void**)&pbrp, g_brp);
    cudaGetSymbolAddress((void**)&pr, g_rb);
    cudaGetSymbolAddress((void**)&ppw, g_pw);
    cudaGetSymbolAddress((void**)&py1, g_y1);
    cudaGetSymbolAddress((void**)&pa, g_a);
    cudaGetSymbolAddress((void**)&py2, g_y2);

    cudaFuncSetAttribute(attn_mma, cudaFuncAttributeMaxDynamicSharedMemorySize, ATTN_SMEM2);
    cudaFuncSetAttribute(gemm_hmma<0>, cudaFuncAttributeMaxDynamicSharedMemorySize, HMMA_SMEM);
    cudaFuncSetAttribute(gemm_hmma<1>, cudaFuncAttributeMaxDynamicSharedMemorySize, HMMA_SMEM);
    cudaFuncSetAttribute(gemm_hmma<2>, cudaFuncAttributeMaxDynamicSharedMemorySize, HMMA_SMEM);
    cudaFuncSetAttribute(gemm_hmma<3>, cudaFuncAttributeMaxDynamicSharedMemorySize, HMMA_SMEM);

    // converts + packs
    conv_split<<<2048, 256>>>(x, pxh, pxl, B_ * L_ * H_);
    conv_split<<<1024, 256>>>(pe, ppeh, ppel, L_ * H_);
    conv_split<<<512, 256>>>(Wc, pWch, pWcl, H_ * H_);
    conv_split<<<512, 256>>>(W1, pW1h, pW1l, H_ * H_);
    conv_split<<<512, 256>>>(W2, pW2h, pW2l, H_ * H_);
    pack_qkvr<<<768, 256>>>(Wq, bq, Wk, bk, Wv, bv, Wr, br);

    // QKV: scatter into fp16 qc/k/v planes (content_bias folded via res=cb)
    gemm_hmma<0><<<dim3(24, 64), 256, HMMA_SMEM>>>(
        pxh, pxl, pBqh, pBql, pbqkv, cb, nullptr, nullptr, nullptr, 1536);

    // R: scatter into float r + fp16 plane
    gemm_hmma<1><<<dim3(8, 16), 256, HMMA_SMEM>>>(
        ppeh, ppel, pBrh, pBrl, pbrp, nullptr, pr, nullptr, nullptr, 512);

    pw_kernel<<<dim3(16, 8), 128>>>(cb, pb, ppw);

    // tensor-core attention (fp16 single-pass)
    attn_mma<<<dim3(32, 32), 256, ATTN_SMEM2>>>();

    // Wc + residual(x) -> y1
    gemm_hmma<2><<<dim3(8, 64), 256, HMMA_SMEM>>>(
        path, patl, pWch, pWcl, bc, x, py1, nullptr, nullptr, 512);

    ln_kernel<true><<<B_ * L_, 256>>>(py1, lnw, lnb, pa, pah, pal);

    // FFN up + GELU -> h1 planes
    gemm_hmma<3><<<dim3(8, 64), 256, HMMA_SMEM>>>(
        pah, pal, pW1h, pW1l, b1, nullptr, nullptr, ph1h, ph1l, 512);

    // FFN down + residual(a) -> y2
    gemm_hmma<2><<<dim3(8, 64), 256, HMMA_SMEM>>>(
        ph1h, ph1l, pW2h, pW2l, b2, pa, py2, nullptr, nullptr, 512);

    ln_kernel<false><<<B_ * L_, 256>>>(py2, lnw, lnb, out, nullptr, nullptr);
}

// round 13
// speedup vs baseline: 3.9198x; 1.3846x over previous
#include <cuda_runtime.h>
#include <cuda_bf16.h>
#include <cuda_fp16.h>
#include <math.h>
#include <stdint.h>

#define B_ 4
#define L_ 2048
#define H_ 512
#define N_ 8
#define D_ 64

typedef unsigned long long ull;

// ================= common helpers =================
__device__ __forceinline__ uint32_t smem_to_u32(const void* p) {
    uint32_t a;
    asm("{ .reg .u64 t; cvta.to.shared.u64 t, %1; cvt.u32.u64 %0, t; }" : "=r"(a) : "l"(p));
    return a;
}

#define LDSM_X4(r, addr)                                                          \
    asm volatile("ldmatrix.sync.aligned.m8n8.x4.shared.b16 {%0,%1,%2,%3}, [%4];"  \
        : "=r"((r)[0]), "=r"((r)[1]), "=r"((r)[2]), "=r"((r)[3]) : "r"(addr))

#define LDSM_X4_T(r, addr)                                                              \
    asm volatile("ldmatrix.sync.aligned.m8n8.x4.trans.shared.b16 {%0,%1,%2,%3}, [%4];"  \
        : "=r"((r)[0]), "=r"((r)[1]), "=r"((r)[2]), "=r"((r)[3]) : "r"(addr))

__device__ __forceinline__ void mma_f16(float* c, const uint32_t* a, uint32_t b0, uint32_t b1) {
    asm volatile(
        "mma.sync.aligned.m16n8k16.row.col.f32.f16.f16.f32 "
        "{%0,%1,%2,%3}, {%4,%5,%6,%7}, {%8,%9}, {%0,%1,%2,%3};"
        : "+f"(c[0]), "+f"(c[1]), "+f"(c[2]), "+f"(c[3])
        : "r"(a[0]), "r"(a[1]), "r"(a[2]), "r"(a[3]), "r"(b0), "r"(b1));
}

#define CP_ASYNC16(dst, src) asm volatile("cp.async.cg.shared.global [%0], [%1], 16;" :: "r"(dst), "l"(src))
#define CP_COMMIT()          asm volatile("cp.async.commit_group;" ::: "memory")
#define CP_WAIT(n)           asm volatile("cp.async.wait_group %0;" :: "n"(n) : "memory")

// ================= scratch (all fp16 single-plane) =================
__device__ __half g_xf[B_ * L_ * H_];
__device__ __half g_pef[L_ * H_];
__device__ __half g_Bqkvf[3 * H_ * H_];
__device__ __half g_Brf[H_ * H_];
__device__ __half g_Wcf[H_ * H_];
__device__ __half g_W1f[H_ * H_];
__device__ __half g_W2f[H_ * H_];
__device__ float g_bqkv[3 * H_];
__device__ float g_brp[H_];
__device__ __half g_qf[32 * L_ * D_];
__device__ __half g_kf[32 * L_ * D_];
__device__ __half g_vf[32 * L_ * D_];
__device__ __half g_rf[N_ * L_ * D_];
__device__ float g_pw[N_ * L_];
__device__ __half g_attnf[B_ * L_ * H_];
__device__ float g_y1[B_ * L_ * H_];
__device__ float g_a[B_ * L_ * H_];
__device__ __half g_af[B_ * L_ * H_];
__device__ __half g_h1f[B_ * L_ * H_];
__device__ float g_y2[B_ * L_ * H_];

// ================= converts / packs =================
__global__ void conv_f16(const float* __restrict__ src, __half* __restrict__ dst, int n) {
    int i = blockIdx.x * 256 + threadIdx.x;
    int stride = gridDim.x * 256;
    for (; i < n; i += stride) dst[i] = __float2half(src[i]);
}

__global__ void pack_qkvr(const float* __restrict__ Wq, const float* __restrict__ bq,
                          const float* __restrict__ Wk, const float* __restrict__ bk,
                          const float* __restrict__ Wv, const float* __restrict__ bv,
                          const float* __restrict__ Wr, const float* __restrict__ br) {
    int idx = blockIdx.x * 256 + threadIdx.x;
    int stride = gridDim.x * 256;
    for (int i = idx; i < 1536 * 512; i += stride) {
        int c = i >> 9, h = i & 511;
        int mat = c >> 9, rem = c & 511, n = rem >> 6, d = rem & 63;
        const float* W = (mat == 0) ? Wq : ((mat == 1) ? Wk : Wv);
        g_Bqkvf[i] = __float2half(W[(n * 512 + h) * 64 + d]);
    }
    for (int i = idx; i < 512 * 512; i += stride) {
        int c = i >> 9, h = i & 511;
        int n = c >> 6, d = c & 63;
        g_Brf[i] = __float2half(Wr[(n * 512 + h) * 64 + d]);
    }
    for (int i = idx; i < 1536; i += stride) {
        int mat = i >> 9, rem = i & 511;
        const float* bb = (mat == 0) ? bq : ((mat == 1) ? bk : bv);
        g_bqkv[i] = bb[rem];
    }
    for (int i = idx; i < 512; i += stride) g_brp[i] = br[i];
}

// pw[n][p] = sum_d (pb-cb)[n][d] * r[n][p][d]  (from fp16 r)
__global__ void pw_kernel(const float* __restrict__ cb, const float* __restrict__ pb,
                          float* __restrict__ pwg) {
    int n = blockIdx.y;
    int p = blockIdx.x * 128 + threadIdx.x;
    const __half* rp = &g_rf[(n * 2048 + p) * 64];
    float s = 0.f;
#pragma unroll 16
    for (int d = 0; d < 64; d++)
        s += (pb[n * 64 + d] - cb[n * 64 + d]) * __half2float(rp[d]);
    pwg[n * 2048 + p] = s;
}

__device__ __forceinline__ float gelu_f(float v) {
    return 0.5f * v * (1.0f + erff(v * 0.70710678118654752f));
}

// ================= HMMA GEMM: 128x64 block, 8 warps 32x32, K=512, single-pass fp16 =================
// MODE 0: qkv scatter (+cb on q via res)  MODE 1: r scatter
// MODE 2: Cf = acc + bias + res           MODE 3: gelu(acc+bias) -> Cg fp16
#define GSTRIDE 80
#define OFF_A 0
#define OFF_B 10240
#define BUF_SZ 15360
#define HMMA_SMEM (2 * BUF_SZ + 128)

template <int MODE>
__global__ void __launch_bounds__(256, 4)
gemm_hmma(const __half* __restrict__ A, const __half* __restrict__ Bm,
          const float* __restrict__ bias, const float* __restrict__ res,
          float* __restrict__ Cf, __half* __restrict__ Cg, int Nc) {
    extern __shared__ char smem[];
    const uint32_t su = smem_to_u32(smem);
    const int tid = threadIdx.x;
    const int wid = tid >> 5, lane = tid & 31;
    const int m0 = blockIdx.y * 128, n0 = blockIdx.x * 64;

    const int wm = (wid & 3) * 32;
    const int wn = (wid >> 2) * 32;

    const uint32_t laneA = (uint32_t)((((lane >> 3) & 1) * 8 + (lane & 7)) * GSTRIDE + (lane >> 4) * 16);
    const uint32_t laneB = (uint32_t)((((lane >> 4) & 1) * 8 + (lane & 7)) * GSTRIDE + ((lane >> 3) & 1) * 16);

    const int arow = tid >> 1;            // 0..127
    const int acb = (tid & 1) * 32;       // byte offset 0/32
    const int brow = tid >> 2;            // 0..63
    const int bcb = (tid & 3) * 16;       // byte offset

    float c[2][4][4];
#pragma unroll
    for (int mi = 0; mi < 2; mi++)
#pragma unroll
        for (int nt = 0; nt < 4; nt++)
#pragma unroll
            for (int e = 0; e < 4; e++) c[mi][nt][e] = 0.f;

    auto issue_stage = [&](int s) {
        const int k0 = s * 32;
        const uint32_t bufo = su + (uint32_t)((s & 1) * BUF_SZ);
        const __half* gA = A + (size_t)(m0 + arow) * 512 + k0 + acb / 2;
        uint32_t dA = bufo + OFF_A + (uint32_t)(arow * GSTRIDE + acb);
        CP_ASYNC16(dA, gA);
        CP_ASYNC16(dA + 16, gA + 8);
        const __half* gB = Bm + (size_t)(n0 + brow) * 512 + k0 + bcb / 2;
        uint32_t dB = bufo + OFF_B + (uint32_t)(brow * GSTRIDE + bcb);
        CP_ASYNC16(dB, gB);
    };

    issue_stage(0);
    CP_COMMIT();

    for (int s = 0; s < 16; s++) {
        if (s + 1 < 16) {
            issue_stage(s + 1);
            CP_COMMIT();
            CP_WAIT(1);
        } else {
            CP_WAIT(0);
        }
        __syncthreads();
        const uint32_t bufo = su + (uint32_t)((s & 1) * BUF_SZ);
#pragma unroll
        for (int ks = 0; ks < 2; ks++) {
            uint32_t a[2][4], bb[2][4];
#pragma unroll
            for (int mi = 0; mi < 2; mi++) {
                uint32_t aaddr = bufo + OFF_A + (uint32_t)((wm + mi * 16) * GSTRIDE + ks * 32) + laneA;
                LDSM_X4(a[mi], aaddr);
            }
#pragma unroll
            for (int ni = 0; ni < 2; ni++) {
                uint32_t baddr = bufo + OFF_B + (uint32_t)((wn + ni * 16) * GSTRIDE + ks * 32) + laneB;
                LDSM_X4(bb[ni], baddr);
            }
#pragma unroll
            for (int mi = 0; mi < 2; mi++)
#pragma unroll
                for (int nt = 0; nt < 4; nt++) {
                    int ni = nt >> 1, sel = (nt & 1) * 2;
                    mma_f16(c[mi][nt], a[mi], bb[ni][sel], bb[ni][sel + 1]);
                }
        }
        __syncthreads();
    }

    // -------- epilogue --------
#pragma unroll
    for (int mi = 0; mi < 2; mi++)
#pragma unroll
        for (int nt = 0; nt < 4; nt++) {
#pragma unroll
            for (int hh = 0; hh < 2; hh++) {
                int m = m0 + wm + mi * 16 + (lane >> 2) + hh * 8;
                int cg = n0 + wn + nt * 8 + (lane & 3) * 2;
                float v0 = c[mi][nt][hh * 2 + 0] + __ldg(&bias[cg]);
                float v1 = c[mi][nt][hh * 2 + 1] + __ldg(&bias[cg + 1]);
                if (MODE == 0) {
                    int mat = cg >> 9, rem = cg & 511, n2 = rem >> 6, d = rem & 63;
                    int bI = m >> 11, l = m & 2047;
                    size_t o = ((size_t)(bI * 8 + n2) * 2048 + l) * 64 + d;
                    if (mat == 0) { v0 += __ldg(&res[rem]); v1 += __ldg(&res[rem + 1]); }
                    __half2 t2;
                    t2.x = __float2half(v0); t2.y = __float2half(v1);
                    if (mat == 0)      *(__half2*)&g_qf[o] = t2;
                    else if (mat == 1) *(__half2*)&g_kf[o] = t2;
                    else               *(__half2*)&g_vf[o] = t2;
                } else if (MODE == 1) {
                    int n2 = cg >> 6, d = cg & 63;
                    size_t o = ((size_t)n2 * 2048 + m) * 64 + d;
                    __half2 t2;
                    t2.x = __float2half(v0); t2.y = __float2half(v1);
                    *(__half2*)&g_rf[o] = t2;
                } else if (MODE == 2) {
                    size_t o = (size_t)m * Nc + cg;
                    Cf[o] = v0 + res[o];
                    Cf[o + 1] = v1 + res[o + 1];
                } else {
                    size_t o = (size_t)m * 512 + cg;
                    __half2 t2;
                    t2.x = __float2half(gelu_f(v0));
                    t2.y = __float2half(gelu_f(v1));
                    *(__half2*)&Cg[o] = t2;
                }
            }
        }
}

// ================= tensor-core flash attention (single-pass fp16) =================
#define AT_STRB 144
#define AO_Q  0
#define AO_K  9216
#define AO_V  18432
#define AO_R  27648
#define AO_P  46080
#define AO_TS 55296
#define AO_PW 90112
#define AO_RM 90624
#define AO_RS 91136
#define ATTN_SMEM2 91648

__global__ void __launch_bounds__(256, 2)
attn_mma() {
    extern __shared__ char sm8[];
    const uint32_t su = smem_to_u32(sm8);
    const int tid = threadIdx.x, wid = tid >> 5, lane = tid & 31;
    const int ib = blockIdx.x, bn = blockIdx.y;
    const int n = bn & 7, b = bn >> 3;
    const int I0 = ib * 64;
    const int wr = (wid & 3) * 16, wc2 = wid >> 2;
    const int rg = lane >> 2, c4 = lane & 3;

    const uint32_t laneA  = (uint32_t)((((lane >> 3) & 1) * 8 + (lane & 7)) * AT_STRB + (lane >> 4) * 16);
    const uint32_t laneB  = (uint32_t)((((lane >> 4) & 1) * 8 + (lane & 7)) * AT_STRB + ((lane >> 3) & 1) * 16);
    const uint32_t laneBT = (uint32_t)((lane & 15) * AT_STRB + (lane >> 4) * 16);

    // load Q once: 64x64 fp16
    {
        const int row = tid >> 2, cb8 = (tid & 3) * 16;
        size_t g = ((size_t)bn * L_ + I0 + row) * 64 + cb8;
        const uint4* s1 = (const uint4*)&g_qf[g];
        uint32_t d0 = (uint32_t)(row * AT_STRB + cb8 * 2);
        *(uint4*)(sm8 + AO_Q + d0) = s1[0];
        *(uint4*)(sm8 + AO_Q + d0 + 16) = s1[1];
    }

    float mrow[2] = {-1e30f, -1e30f};
    float lsum[2] = {0.f, 0.f};
    float o[4][4];
#pragma unroll
    for (int nt = 0; nt < 4; nt++)
#pragma unroll
        for (int e = 0; e < 4; e++) o[nt][e] = 0.f;

    for (int jb = 0; jb <= ib; jb++) {
        const int J0 = jb * 64;
        const int pmin = L_ - 64 - I0 + J0;
        __syncthreads();
        {
            const int row = tid >> 2, cb8 = (tid & 3) * 16;
            uint32_t d0 = (uint32_t)(row * AT_STRB + cb8 * 2);
            size_t gk = ((size_t)bn * L_ + J0 + row) * 64 + cb8;
            const uint4* s1 = (const uint4*)&g_kf[gk];
            const uint4* s3 = (const uint4*)&g_vf[gk];
            *(uint4*)(sm8 + AO_K + d0) = s1[0]; *(uint4*)(sm8 + AO_K + d0 + 16) = s1[1];
            *(uint4*)(sm8 + AO_V + d0) = s3[0]; *(uint4*)(sm8 + AO_V + d0 + 16) = s3[1];
#pragma unroll
            for (int t = 0; t < 2; t++) {
                int pp = row + t * 64;
                int p = pmin + pp;
                uint32_t dr = (uint32_t)(pp * AT_STRB + cb8 * 2);
                uint4 r0 = make_uint4(0, 0, 0, 0), r1 = r0;
                if (p < L_) {
                    size_t gr = ((size_t)n * L_ + p) * 64 + cb8;
                    const uint4* t1 = (const uint4*)&g_rf[gr];
                    r0 = t1[0]; r1 = t1[1];
                }
                *(uint4*)(sm8 + AO_R + dr) = r0; *(uint4*)(sm8 + AO_R + dr + 16) = r1;
            }
            if (tid < 128) {
                int p = pmin + tid;
                *(float*)(sm8 + AO_PW + tid * 4) = (p < L_) ? g_pw[n * 2048 + p] : 0.f;
            }
        }
        __syncthreads();

        // ---- QK (regs) + T (-> Ts smem) ----
        float sQK[4][4], tacc[8][4];
#pragma unroll
        for (int nt = 0; nt < 4; nt++)
#pragma unroll
            for (int e = 0; e < 4; e++) sQK[nt][e] = 0.f;
#pragma unroll
        for (int nt = 0; nt < 8; nt++)
#pragma unroll
            for (int e = 0; e < 4; e++) tacc[nt][e] = 0.f;

#pragma unroll
        for (int ks = 0; ks < 4; ks++) {
            uint32_t aq[4];
            uint32_t abase = su + (uint32_t)(wr * AT_STRB + ks * 32) + laneA;
            LDSM_X4(aq, abase + AO_Q);
            uint32_t kb[2][4];
#pragma unroll
            for (int f = 0; f < 2; f++) {
                uint32_t baddr = su + (uint32_t)((wc2 * 32 + f * 16) * AT_STRB + ks * 32) + laneB;
                LDSM_X4(kb[f], baddr + AO_K);
            }
#pragma unroll
            for (int nt = 0; nt < 4; nt++) {
                int f = nt >> 1, sel = (nt & 1) * 2;
                mma_f16(sQK[nt], aq, kb[f][sel], kb[f][sel + 1]);
            }
            uint32_t rb[4][4];
#pragma unroll
            for (int f = 0; f < 4; f++) {
                uint32_t baddr = su + (uint32_t)((wc2 * 64 + f * 16) * AT_STRB + ks * 32) + laneB;
                LDSM_X4(rb[f], baddr + AO_R);
            }
#pragma unroll
            for (int nt = 0; nt < 8; nt++) {
                int f = nt >> 1, sel = (nt & 1) * 2;
                mma_f16(tacc[nt], aq, rb[f][sel], rb[f][sel + 1]);
            }
        }
#pragma unroll
        for (int nt = 0; nt < 8; nt++) {
#pragma unroll
            for (int e = 0; e < 4; e++) {
                int row = wr + rg + (e >> 1) * 8;
                int col = wc2 * 64 + nt * 8 + c4 * 2 + (e & 1);
                *(float*)(sm8 + AO_TS + (row * 136 + col) * 4) =
                    tacc[nt][e] + *(float*)(sm8 + AO_PW + col * 4);
            }
        }
        __syncthreads();

        // ---- softmax ----
        const bool diag = (jb == ib);
        float s[4][4];
        float wmax[2] = {-1e30f, -1e30f};
#pragma unroll
        for (int nt = 0; nt < 4; nt++) {
#pragma unroll
            for (int e = 0; e < 4; e++) {
                int ii = wr + rg + (e >> 1) * 8;
                int jj = wc2 * 32 + nt * 8 + c4 * 2 + (e & 1);
                float v = sQK[nt][e] + *(float*)(sm8 + AO_TS + (ii * 136 + (63 - ii + jj)) * 4);
                v *= 0.125f;
                if (diag && jj > ii) v = -1e30f;
                s[nt][e] = v;
                wmax[e >> 1] = fmaxf(wmax[e >> 1], v);
            }
        }
#pragma unroll
        for (int h = 0; h < 2; h++) {
            wmax[h] = fmaxf(wmax[h], __shfl_xor_sync(0xffffffffu, wmax[h], 1));
            wmax[h] = fmaxf(wmax[h], __shfl_xor_sync(0xffffffffu, wmax[h], 2));
        }
        if (c4 == 0) {
            *(float*)(sm8 + AO_RM + (wc2 * 64 + wr + rg) * 4) = wmax[0];
            *(float*)(sm8 + AO_RM + (wc2 * 64 + wr + rg + 8) * 4) = wmax[1];
        }
        __syncthreads();
        float alpha[2], mnew[2];
#pragma unroll
        for (int h = 0; h < 2; h++) {
            float other = *(float*)(sm8 + AO_RM + ((1 - wc2) * 64 + wr + rg + h * 8) * 4);
            mnew[h] = fmaxf(mrow[h], fmaxf(wmax[h], other));
            alpha[h] = __expf(mrow[h] - mnew[h]);
            mrow[h] = mnew[h];
        }
        float rsum[2] = {0.f, 0.f};
#pragma unroll
        for (int nt = 0; nt < 4; nt++) {
#pragma unroll
            for (int h = 0; h < 2; h++) {
                float p0 = __expf(s[nt][h * 2 + 0] - mnew[h]);
                float p1 = __expf(s[nt][h * 2 + 1] - mnew[h]);
                rsum[h] += p0 + p1;
                int ii = wr + rg + h * 8;
                int jj = wc2 * 32 + nt * 8 + c4 * 2;
                __half2 t2;
                t2.x = __float2half(p0); t2.y = __float2half(p1);
                *(__half2*)(sm8 + AO_P + ii * AT_STRB + jj * 2) = t2;
            }
        }
#pragma unroll
        for (int h = 0; h < 2; h++) {
            rsum[h] += __shfl_xor_sync(0xffffffffu, rsum[h], 1);
            rsum[h] += __shfl_xor_sync(0xffffffffu, rsum[h], 2);
        }
        if (c4 == 0) {
            *(float*)(sm8 + AO_RS + (wc2 * 64 + wr + rg) * 4) = rsum[0];
            *(float*)(sm8 + AO_RS + (wc2 * 64 + wr + rg + 8) * 4) = rsum[1];
        }
#pragma unroll
        for (int nt = 0; nt < 4; nt++) {
            o[nt][0] *= alpha[0]; o[nt][1] *= alpha[0];
            o[nt][2] *= alpha[1]; o[nt][3] *= alpha[1];
        }
        __syncthreads();
#pragma unroll
        for (int h = 0; h < 2; h++) {
            int row = wr + rg + h * 8;
            float tot = *(float*)(sm8 + AO_RS + row * 4) +
                        *(float*)(sm8 + AO_RS + (64 + row) * 4);
            lsum[h] = lsum[h] * alpha[h] + tot;
        }

        // ---- PV ----
#pragma unroll
        for (int ks = 0; ks < 4; ks++) {
            uint32_t pa[4];
            uint32_t abase = su + (uint32_t)(wr * AT_STRB + ks * 32) + laneA;
            LDSM_X4(pa, abase + AO_P);
            uint32_t vb[2][4];
#pragma unroll
            for (int f = 0; f < 2; f++) {
                uint32_t baddr = su + (uint32_t)((ks * 16) * AT_STRB + (wc2 * 32 + f * 16) * 2) + laneBT;
                LDSM_X4_T(vb[f], baddr + AO_V);
            }
#pragma unroll
            for (int nt = 0; nt < 4; nt++) {
                int f = nt >> 1, sel = (nt & 1) * 2;
                mma_f16(o[nt], pa, vb[f][sel], vb[f][sel + 1]);
            }
        }
    }

    // ---- epilogue: normalize, store fp16 attn ----
    float inv0 = 1.f / lsum[0], inv1 = 1.f / lsum[1];
#pragma unroll
    for (int nt = 0; nt < 4; nt++) {
        int d = wc2 * 32 + nt * 8 + c4 * 2;
        int r0g = I0 + wr + rg;
        size_t o0 = ((size_t)b * L_ + r0g) * 512 + n * 64 + d;
        size_t o1 = ((size_t)b * L_ + r0g + 8) * 512 + n * 64 + d;
        __half2 t2;
        t2.x = __float2half(o[nt][0] * inv0);
        t2.y = __float2half(o[nt][1] * inv0);
        *(__half2*)&g_attnf[o0] = t2;
        t2.x = __float2half(o[nt][2] * inv1);
        t2.y = __float2half(o[nt][3] * inv1);
        *(__half2*)&g_attnf[o1] = t2;
    }
}

// ================= layernorm (eps=1e-12) =================
template <bool TOF16>
__global__ void ln_kernel(const float* __restrict__ in, const float* __restrict__ w,
                          const float* __restrict__ bparm, float* __restrict__ out,
                          __half* __restrict__ of16) {
    __shared__ float red[8];
    __shared__ float stat[2];
    int row = blockIdx.x, tid = threadIdx.x;
    const float* xr = in + (size_t)row * H_;
    float v0 = xr[tid], v1 = xr[tid + 256];
    float s = v0 + v1;
#pragma unroll
    for (int mk = 16; mk >= 1; mk >>= 1) s += __shfl_xor_sync(0xffffffffu, s, mk);
    if ((tid & 31) == 0) red[tid >> 5] = s;
    __syncthreads();
    if (tid == 0) {
        float t = 0;
#pragma unroll
        for (int i = 0; i < 8; i++) t += red[i];
        stat[0] = t * (1.0f / H_);
    }
    __syncthreads();
    float u = stat[0];
    float d0 = v0 - u, d1 = v1 - u;
    float q = d0 * d0 + d1 * d1;
#pragma unroll
    for (int mk = 16; mk >= 1; mk >>= 1) q += __shfl_xor_sync(0xffffffffu, q, mk);
    __syncthreads();
    if ((tid & 31) == 0) red[tid >> 5] = q;
    __syncthreads();
    if (tid == 0) {
        float t = 0;
#pragma unroll
        for (int i = 0; i < 8; i++) t += red[i];
        stat[1] = rsqrtf(t * (1.0f / H_) + 1e-12f);
    }
    __syncthreads();
    float inv = stat[1];
    float r0v = w[tid] * d0 * inv + bparm[tid];
    float r1v = w[tid + 256] * d1 * inv + bparm[tid + 256];
    out[(size_t)row * H_ + tid] = r0v;
    out[(size_t)row * H_ + tid + 256] = r1v;
    if (TOF16) {
        of16[(size_t)row * H_ + tid] = __float2half(r0v);
        of16[(size_t)row * H_ + tid + 256] = __float2half(r1v);
    }
}

// ================= launch =================
extern "C" void kernel_launch(void* const* d_in, const int* in_sizes, int n_in,
                              void* d_out, int out_size) {
    (void)in_sizes; (void)n_in; (void)out_size;
    const float* x  = (const float*)d_in[0];
    const float* pe = (const float*)d_in[1];
    const float* Wq = (const float*)d_in[2];
    const float* bq = (const float*)d_in[3];
    const float* Wk = (const float*)d_in[4];
    const float* bk = (const float*)d_in[5];
    const float* Wv = (const float*)d_in[6];
    const float* bv = (const float*)d_in[7];
    const float* Wr = (const float*)d_in[8];
    const float* br = (const float*)d_in[9];
    const float* cb = (const float*)d_in[10];
    const float* pb = (const float*)d_in[11];
    const float* Wc = (const float*)d_in[12];
    const float* bc = (const float*)d_in[13];
    const float* W1 = (const float*)d_in[14];
    const float* b1 = (const float*)d_in[15];
    const float* W2 = (const float*)d_in[16];
    const float* b2 = (const float*)d_in[17];
    const float* lnw = (const float*)d_in[18];
    const float* lnb = (const float*)d_in[19];
    float* out = (float*)d_out;

    __half *pxf, *ppef, *pBqf, *pBrf, *pWcf, *pW1f, *pW2f, *patf, *paf, *ph1f;
    float *pbqkv, *pbrp, *ppw, *py1, *pa, *py2;
    cudaGetSymbolAddress((void**)&pxf, g_xf);
    cudaGetSymbolAddress((void**)&ppef, g_pef);
    cudaGetSymbolAddress((void**)&pBqf, g_Bqkvf);
    cudaGetSymbolAddress((void**)&pBrf, g_Brf);
    cudaGetSymbolAddress((void**)&pWcf, g_Wcf);
    cudaGetSymbolAddress((void**)&pW1f, g_W1f);
    cudaGetSymbolAddress((void**)&pW2f, g_W2f);
    cudaGetSymbolAddress((void**)&patf, g_attnf);
    cudaGetSymbolAddress((void**)&paf, g_af);
    cudaGetSymbolAddress((void**)&ph1f, g_h1f);
    cudaGetSymbolAddress((void**)&pbqkv, g_bqkv);
    cudaGetSymbolAddress((void**)&pbrp, g_brp);
    cudaGetSymbolAddress((void**)&ppw, g_pw);
    cudaGetSymbolAddress((void**)&py1, g_y1);
    cudaGetSymbolAddress((void**)&pa, g_a);
    cudaGetSymbolAddress((void**)&py2, g_y2);

    cudaFuncSetAttribute(attn_mma, cudaFuncAttributeMaxDynamicSharedMemorySize, ATTN_SMEM2);
    cudaFuncSetAttribute(gemm_hmma<0>, cudaFuncAttributeMaxDynamicSharedMemorySize, HMMA_SMEM);
    cudaFuncSetAttribute(gemm_hmma<1>, cudaFuncAttributeMaxDynamicSharedMemorySize, HMMA_SMEM);
    cudaFuncSetAttribute(gemm_hmma<2>, cudaFuncAttributeMaxDynamicSharedMemorySize, HMMA_SMEM);
    cudaFuncSetAttribute(gemm_hmma<3>, cudaFuncAttributeMaxDynamicSharedMemorySize, HMMA_SMEM);

    // converts + packs
    conv_f16<<<2048, 256>>>(x, pxf, B_ * L_ * H_);
    conv_f16<<<1024, 256>>>(pe, ppef, L_ * H_);
    conv_f16<<<256, 256>>>(Wc, pWcf, H_ * H_);
    conv_f16<<<256, 256>>>(W1, pW1f, H_ * H_);
    conv_f16<<<256, 256>>>(W2, pW2f, H_ * H_);
    pack_qkvr<<<768, 256>>>(Wq, bq, Wk, bk, Wv, bv, Wr, br);

    // QKV: scatter into fp16 qc/k/v (content_bias folded via res=cb)
    gemm_hmma<0><<<dim3(24, 64), 256, HMMA_SMEM>>>(
        pxf, pBqf, pbqkv, cb, nullptr, nullptr, 1536);

    // R: scatter into fp16 r
    gemm_hmma<1><<<dim3(8, 16), 256, HMMA_SMEM>>>(
        ppef, pBrf, pbrp, nullptr, nullptr, nullptr, 512);

    pw_kernel<<<dim3(16, 8), 128>>>(cb, pb, ppw);

    // tensor-core attention (fp16 single-pass)
    attn_mma<<<dim3(32, 32), 256, ATTN_SMEM2>>>();

    // Wc + residual(x) -> y1
    gemm_hmma<2><<<dim3(8, 64), 256, HMMA_SMEM>>>(
        patf, pWcf, bc, x, py1, nullptr, 512);

    ln_kernel<true><<<B_ * L_, 256>>>(py1, lnw, lnb, pa, paf);

    // FFN up + GELU -> h1 fp16
    gemm_hmma<3><<<dim3(8, 64), 256, HMMA_SMEM>>>(
        paf, pW1f, b1, nullptr, nullptr, ph1f, 512);

    // FFN down + residual(a) -> y2
    gemm_hmma<2><<<dim3(8, 64), 256, HMMA_SMEM>>>(
        ph1f, pW2f, b2, pa, py2, nullptr, 512);

    ln_kernel<false><<<B_ * L_, 256>>>(py2, lnw, lnb, out, nullptr);
}